// round 1
// baseline (speedup 1.0000x reference)
#include <cuda_runtime.h>

#define HID 128
#define NGRAPHS 1024
#define ZD 56

// Scratch (graph encoder is the largest user; tree reuses the same buffers).
__device__ float g_h   [100000 * 128];
__device__ float g_A   [100000 * 128];
__device__ float g_B   [100000 * 128];
__device__ float g_aggr[100000 * 128];
__device__ float g_sums[NGRAPHS * 128];
__device__ float g_cnt [NGRAPHS];

// ---------------------------------------------------------------------------
// Y[M,128] = act(X[M,K] @ W[K,128] + bias), K in {32,64,128} (K % 32 == 0).
// Block: 256 threads, tile 64 rows x 128 cols, each thread: 8 rows x 4 cols.
// ---------------------------------------------------------------------------
__global__ void gemm128(const float* __restrict__ X, const float* __restrict__ W,
                        const float* __restrict__ bias, float* __restrict__ Y,
                        int M, int K, int do_relu)
{
    __shared__ float sX[64 * 128];   // 32 KB (row stride 128 regardless of K)
    __shared__ float sW[32 * 128];   // 16 KB
    const int tid = threadIdx.x;
    const int tx = tid & 31;         // 4-col group
    const int ty = tid >> 5;         // 8-row group
    const int row0 = blockIdx.x * 64;

    // Stage X tile
    for (int i = tid; i < 64 * K; i += 256) {
        int r = i / K, k = i - r * K;
        int row = row0 + r;
        sX[r * 128 + k] = (row < M) ? X[(size_t)row * K + k] : 0.0f;
    }

    float acc[8][4];
#pragma unroll
    for (int r = 0; r < 8; r++)
#pragma unroll
        for (int c = 0; c < 4; c++) acc[r][c] = 0.0f;

    __syncthreads();

    for (int k0 = 0; k0 < K; k0 += 32) {
        // Stage 32 rows of W (W is K x 128 row-major, so chunk is contiguous)
        for (int i = tid; i < 32 * 128; i += 256)
            sW[i] = W[k0 * 128 + i];
        __syncthreads();

#pragma unroll
        for (int kk = 0; kk < 32; kk++) {
            float4 w = *(const float4*)(sW + kk * 128 + tx * 4);
#pragma unroll
            for (int r = 0; r < 8; r++) {
                float a = sX[(ty * 8 + r) * 128 + k0 + kk];  // warp broadcast
                acc[r][0] += a * w.x;
                acc[r][1] += a * w.y;
                acc[r][2] += a * w.z;
                acc[r][3] += a * w.w;
            }
        }
        __syncthreads();
    }

    float4 bv = make_float4(0.f, 0.f, 0.f, 0.f);
    if (bias) bv = *(const float4*)(bias + tx * 4);

#pragma unroll
    for (int r = 0; r < 8; r++) {
        int row = row0 + ty * 8 + r;
        if (row < M) {
            float4 o;
            o.x = acc[r][0] + bv.x;
            o.y = acc[r][1] + bv.y;
            o.z = acc[r][2] + bv.z;
            o.w = acc[r][3] + bv.w;
            if (do_relu) {
                o.x = fmaxf(o.x, 0.f); o.y = fmaxf(o.y, 0.f);
                o.z = fmaxf(o.z, 0.f); o.w = fmaxf(o.w, 0.f);
            }
            *(float4*)(Y + (size_t)row * 128 + tx * 4) = o;
        }
    }
}

// ---------------------------------------------------------------------------
// Per-edge: aggr[dst] += relu(A[dst] + B[src])   (bias pre-folded into A)
// One warp per edge, float4 per lane, vector red to cut atomic-op count 4x.
// ---------------------------------------------------------------------------
__global__ void edge_agg(const int* __restrict__ ei, int E,
                         const float* __restrict__ A, const float* __restrict__ B,
                         float* __restrict__ aggr)
{
    int w = (blockIdx.x * blockDim.x + threadIdx.x) >> 5;
    int lane = threadIdx.x & 31;
    if (w >= E) return;
    int src = __ldg(ei + w);
    int dst = __ldg(ei + E + w);
    float4 a = *(const float4*)(A + (size_t)dst * 128 + lane * 4);
    float4 b = *(const float4*)(B + (size_t)src * 128 + lane * 4);
    float4 v;
    v.x = fmaxf(a.x + b.x, 0.f);
    v.y = fmaxf(a.y + b.y, 0.f);
    v.z = fmaxf(a.z + b.z, 0.f);
    v.w = fmaxf(a.w + b.w, 0.f);
    float* p = aggr + (size_t)dst * 128 + lane * 4;
    asm volatile("red.global.add.v4.f32 [%0], {%1,%2,%3,%4};"
                 :: "l"(p), "f"(v.x), "f"(v.y), "f"(v.z), "f"(v.w) : "memory");
}

// ---------------------------------------------------------------------------
// Mean pool: sums[batch[n]] += h[n]; cnt[batch[n]] += 1
// ---------------------------------------------------------------------------
__global__ void pool_sum(const float* __restrict__ hin, const int* __restrict__ batch,
                         int n, float* __restrict__ sums, float* __restrict__ cnt)
{
    int w = (blockIdx.x * blockDim.x + threadIdx.x) >> 5;
    int lane = threadIdx.x & 31;
    if (w >= n) return;
    int g = __ldg(batch + w);
    float4 v = *(const float4*)(hin + (size_t)w * 128 + lane * 4);
    float* p = sums + (size_t)g * 128 + lane * 4;
    asm volatile("red.global.add.v4.f32 [%0], {%1,%2,%3,%4};"
                 :: "l"(p), "f"(v.x), "f"(v.y), "f"(v.z), "f"(v.w) : "memory");
    if (lane == 0) atomicAdd(cnt + g, 1.0f);
}

__global__ void pool_div(const float* __restrict__ sums, const float* __restrict__ cnt,
                         float* __restrict__ fused, int colofs)
{
    int g = blockIdx.x, c = threadIdx.x;
    float cc = fmaxf(cnt[g], 1.0f);
    fused[(size_t)g * 256 + colofs + c] = sums[(size_t)g * 128 + c] / cc;
}

// ---------------------------------------------------------------------------
// Heads: mu = fused @ mu_w + mu_b ; logvar = fused @ lv_w + lv_b
// One block per graph row; threads 0..55 -> mu, 56..111 -> logvar.
// ---------------------------------------------------------------------------
__global__ void head_kernel(const float* __restrict__ fused,
                            const float* __restrict__ mu_w, const float* __restrict__ mu_b,
                            const float* __restrict__ lv_w, const float* __restrict__ lv_b,
                            float* __restrict__ mu_out, float* __restrict__ lv_out)
{
    __shared__ float sf[256];
    int g = blockIdx.x, t = threadIdx.x;
    sf[t]       = fused[(size_t)g * 256 + t];
    sf[t + 128] = fused[(size_t)g * 256 + 128 + t];
    __syncthreads();
    if (t < 112) {
        bool is_mu = (t < 56);
        int j = is_mu ? t : t - 56;
        const float* Wp = is_mu ? mu_w : lv_w;
        float acc = is_mu ? mu_b[j] : lv_b[j];
#pragma unroll 8
        for (int k = 0; k < 256; k++) acc += sf[k] * Wp[k * ZD + j];
        if (is_mu) mu_out[(size_t)g * ZD + j] = acc;
        else       lv_out[(size_t)g * ZD + j] = acc;
    }
}

// ---------------------------------------------------------------------------
extern "C" void kernel_launch(void* const* d_in, const int* in_sizes, int n_in,
                              void* d_out, int out_size)
{
    const float* tree_x      = (const float*)d_in[0];
    const int*   tree_ei     = (const int*)  d_in[1];
    const float* graph_x     = (const float*)d_in[2];
    const int*   graph_ei    = (const int*)  d_in[3];
    const int*   batch_tree  = (const int*)  d_in[4];
    const int*   batch_graph = (const int*)  d_in[5];
    const float* t_proj_w = (const float*)d_in[6];
    const float* t_proj_b = (const float*)d_in[7];
    const float* t_msg_w  = (const float*)d_in[8];
    const float* t_msg_b  = (const float*)d_in[9];
    const float* t_lin_w  = (const float*)d_in[10];
    const float* t_lin_b  = (const float*)d_in[11];
    const float* gr_proj_w = (const float*)d_in[12];
    const float* gr_proj_b = (const float*)d_in[13];
    const float* gr_msg_w  = (const float*)d_in[14];
    const float* gr_msg_b  = (const float*)d_in[15];
    const float* gr_lin_w  = (const float*)d_in[16];
    const float* gr_lin_b  = (const float*)d_in[17];
    const float* mu_w = (const float*)d_in[18];
    const float* mu_b = (const float*)d_in[19];
    const float* lv_w = (const float*)d_in[20];
    const float* lv_b = (const float*)d_in[21];
    float* out = (float*)d_out;

    const int n_tree  = in_sizes[0] / 64;
    const int e_tree  = in_sizes[1] / 2;
    const int n_graph = in_sizes[2] / 32;
    const int e_graph = in_sizes[3] / 2;

    float *h, *A, *B, *aggr, *sums, *cnt;
    cudaGetSymbolAddress((void**)&h,    g_h);
    cudaGetSymbolAddress((void**)&A,    g_A);
    cudaGetSymbolAddress((void**)&B,    g_B);
    cudaGetSymbolAddress((void**)&aggr, g_aggr);
    cudaGetSymbolAddress((void**)&sums, g_sums);
    cudaGetSymbolAddress((void**)&cnt,  g_cnt);

    float* fused = out + 2 * NGRAPHS * ZD;   // output layout: mu | logvar | fused

    auto encode = [&](const float* x, int n, int din, const int* ei, int E,
                      const int* batch, const float* pw, const float* pb,
                      const float* mw, const float* mb,
                      const float* lw, const float* lb, int colofs) {
        int gb = (n + 63) / 64;
        // input projection with relu
        gemm128<<<gb, 256>>>(x, pw, pb, h, n, din, 1);
        for (int l = 0; l < 3; l++) {
            // A = h @ W_top + msg_b   (dst-side contribution, bias folded in)
            gemm128<<<gb, 256>>>(h, mw + (size_t)l * 256 * 128, mb + l * 128, A, n, 128, 0);
            // B = h @ W_bot           (src-side contribution)
            gemm128<<<gb, 256>>>(h, mw + (size_t)l * 256 * 128 + 128 * 128, nullptr, B, n, 128, 0);
            cudaMemsetAsync(aggr, 0, (size_t)n * 128 * sizeof(float));
            int eb = (int)(((long long)E * 32 + 255) / 256);
            edge_agg<<<eb, 256>>>(ei, E, A, B, aggr);
            // h = relu(aggr @ lin_w + lin_b)
            gemm128<<<gb, 256>>>(aggr, lw + (size_t)l * 128 * 128, lb + l * 128, h, n, 128, 1);
        }
        cudaMemsetAsync(sums, 0, (size_t)NGRAPHS * 128 * sizeof(float));
        cudaMemsetAsync(cnt,  0, (size_t)NGRAPHS * sizeof(float));
        int pbk = (int)(((long long)n * 32 + 255) / 256);
        pool_sum<<<pbk, 256>>>(h, batch, n, sums, cnt);
        pool_div<<<NGRAPHS, 128>>>(sums, cnt, fused, colofs);
    };

    encode(tree_x,  n_tree,  64, tree_ei,  e_tree,  batch_tree,
           t_proj_w, t_proj_b, t_msg_w, t_msg_b, t_lin_w, t_lin_b, 0);
    encode(graph_x, n_graph, 32, graph_ei, e_graph, batch_graph,
           gr_proj_w, gr_proj_b, gr_msg_w, gr_msg_b, gr_lin_w, gr_lin_b, 128);

    head_kernel<<<NGRAPHS, 128>>>(fused, mu_w, mu_b, lv_w, lv_b,
                                  out, out + NGRAPHS * ZD);
}

// round 2
// speedup vs baseline: 1.8637x; 1.8637x over previous
#include <cuda_runtime.h>
#include <cstdint>

#define HID 128
#define NGRAPHS 1024
#define ZD 56

// Scratch (graph encoder is the largest user; tree reuses the same buffers).
__device__ float g_h   [100000 * 128];
__device__ float g_A   [100000 * 128];
__device__ float g_B   [100000 * 128];
__device__ float g_aggr[100000 * 128];
__device__ float g_sums[NGRAPHS * 128];
__device__ float g_cnt [NGRAPHS];

__device__ __forceinline__ uint32_t f2tf32(float v) {
    uint32_t t;
    asm("cvt.rna.tf32.f32 %0, %1;" : "=r"(t) : "f"(v));
    return t;
}

// ---------------------------------------------------------------------------
// Y[M,128] = act(X[M,K] @ W[K,128] + bias), K in {32,64,128} (K % 32 == 0).
// tf32 tensor-core GEMM. Block tile 128x128, 8 warps, warp tile 32x64.
// mma.sync m16n8k8 tf32, fp32 accumulate.
// ---------------------------------------------------------------------------
__global__ __launch_bounds__(256, 2)
void gemm_tf32(const float* __restrict__ X, const float* __restrict__ W,
               const float* __restrict__ bias, float* __restrict__ Y,
               int M, int K, int do_relu)
{
    __shared__ uint32_t sX[128 * 36];   // 128 rows x 32 k, stride 36 (pad)
    __shared__ uint32_t sW[32 * 136];   // 32 k x 128 n, stride 136 (pad)
    const int tid  = threadIdx.x;
    const int warp = tid >> 5, lane = tid & 31;
    const int g  = lane >> 2;           // 0..7
    const int tg = lane & 3;            // 0..3
    const int wm = (warp >> 1) * 32;    // warp row offset within tile: 0,32,64,96
    const int wn = (warp & 1) * 64;     // warp col offset within tile: 0,64
    const int row0 = blockIdx.x * 128;

    float c[2][8][4];
#pragma unroll
    for (int mi = 0; mi < 2; mi++)
#pragma unroll
        for (int ni = 0; ni < 8; ni++)
#pragma unroll
            for (int q = 0; q < 4; q++) c[mi][ni][q] = 0.0f;

    for (int k0 = 0; k0 < K; k0 += 32) {
        // Stage X chunk: 128 rows x 32 k (guard rows, cvt to tf32)
#pragma unroll
        for (int i = tid; i < 128 * 32; i += 256) {
            int r = i >> 5, k = i & 31;
            int row = row0 + r;
            float v = (row < M) ? X[(size_t)row * K + k0 + k] : 0.0f;
            sX[r * 36 + k] = f2tf32(v);
        }
        // Stage W chunk: 32 k x 128 n (contiguous rows of W)
#pragma unroll
        for (int i = tid; i < 32 * 128; i += 256) {
            int kk = i >> 7, n = i & 127;
            sW[kk * 136 + n] = f2tf32(W[(size_t)(k0 + kk) * 128 + n]);
        }
        __syncthreads();

#pragma unroll
        for (int kk = 0; kk < 32; kk += 8) {
            uint32_t a[2][4], b[8][2];
#pragma unroll
            for (int mi = 0; mi < 2; mi++) {
                int r = wm + mi * 16 + g;
                a[mi][0] = sX[r * 36 + kk + tg];
                a[mi][1] = sX[(r + 8) * 36 + kk + tg];
                a[mi][2] = sX[r * 36 + kk + tg + 4];
                a[mi][3] = sX[(r + 8) * 36 + kk + tg + 4];
            }
#pragma unroll
            for (int ni = 0; ni < 8; ni++) {
                int n = wn + ni * 8 + g;
                b[ni][0] = sW[(kk + tg) * 136 + n];
                b[ni][1] = sW[(kk + tg + 4) * 136 + n];
            }
#pragma unroll
            for (int mi = 0; mi < 2; mi++)
#pragma unroll
                for (int ni = 0; ni < 8; ni++) {
                    asm volatile(
                        "mma.sync.aligned.m16n8k8.row.col.f32.tf32.tf32.f32 "
                        "{%0,%1,%2,%3},{%4,%5,%6,%7},{%8,%9},{%0,%1,%2,%3};"
                        : "+f"(c[mi][ni][0]), "+f"(c[mi][ni][1]),
                          "+f"(c[mi][ni][2]), "+f"(c[mi][ni][3])
                        : "r"(a[mi][0]), "r"(a[mi][1]), "r"(a[mi][2]), "r"(a[mi][3]),
                          "r"(b[ni][0]), "r"(b[ni][1]));
                }
        }
        __syncthreads();
    }

    // Epilogue: bias + relu + store (float2 per fragment half-row)
#pragma unroll
    for (int mi = 0; mi < 2; mi++) {
#pragma unroll
        for (int half = 0; half < 2; half++) {
            int row = row0 + wm + mi * 16 + g + half * 8;
            if (row < M) {
#pragma unroll
                for (int ni = 0; ni < 8; ni++) {
                    int col = wn + ni * 8 + tg * 2;
                    float2 o;
                    o.x = c[mi][ni][half * 2 + 0];
                    o.y = c[mi][ni][half * 2 + 1];
                    if (bias) { o.x += bias[col]; o.y += bias[col + 1]; }
                    if (do_relu) { o.x = fmaxf(o.x, 0.f); o.y = fmaxf(o.y, 0.f); }
                    *(float2*)(Y + (size_t)row * 128 + col) = o;
                }
            }
        }
    }
}

// ---------------------------------------------------------------------------
// Per-edge: aggr[dst] += relu(A[dst] + B[src])   (bias pre-folded into A)
// One warp per edge, float4 per lane, vector red to cut atomic-op count 4x.
// ---------------------------------------------------------------------------
__global__ void edge_agg(const int* __restrict__ ei, int E,
                         const float* __restrict__ A, const float* __restrict__ B,
                         float* __restrict__ aggr)
{
    int w = (blockIdx.x * blockDim.x + threadIdx.x) >> 5;
    int lane = threadIdx.x & 31;
    if (w >= E) return;
    int src = __ldg(ei + w);
    int dst = __ldg(ei + E + w);
    float4 a = *(const float4*)(A + (size_t)dst * 128 + lane * 4);
    float4 b = *(const float4*)(B + (size_t)src * 128 + lane * 4);
    float4 v;
    v.x = fmaxf(a.x + b.x, 0.f);
    v.y = fmaxf(a.y + b.y, 0.f);
    v.z = fmaxf(a.z + b.z, 0.f);
    v.w = fmaxf(a.w + b.w, 0.f);
    float* p = aggr + (size_t)dst * 128 + lane * 4;
    asm volatile("red.global.add.v4.f32 [%0], {%1,%2,%3,%4};"
                 :: "l"(p), "f"(v.x), "f"(v.y), "f"(v.z), "f"(v.w) : "memory");
}

// ---------------------------------------------------------------------------
// Mean pool: sums[batch[n]] += h[n]; cnt[batch[n]] += 1
// ---------------------------------------------------------------------------
__global__ void pool_sum(const float* __restrict__ hin, const int* __restrict__ batch,
                         int n, float* __restrict__ sums, float* __restrict__ cnt)
{
    int w = (blockIdx.x * blockDim.x + threadIdx.x) >> 5;
    int lane = threadIdx.x & 31;
    if (w >= n) return;
    int g = __ldg(batch + w);
    float4 v = *(const float4*)(hin + (size_t)w * 128 + lane * 4);
    float* p = sums + (size_t)g * 128 + lane * 4;
    asm volatile("red.global.add.v4.f32 [%0], {%1,%2,%3,%4};"
                 :: "l"(p), "f"(v.x), "f"(v.y), "f"(v.z), "f"(v.w) : "memory");
    if (lane == 0) atomicAdd(cnt + g, 1.0f);
}

__global__ void pool_div(const float* __restrict__ sums, const float* __restrict__ cnt,
                         float* __restrict__ fused, int colofs)
{
    int g = blockIdx.x, c = threadIdx.x;
    float cc = fmaxf(cnt[g], 1.0f);
    fused[(size_t)g * 256 + colofs + c] = sums[(size_t)g * 128 + c] / cc;
}

// ---------------------------------------------------------------------------
// Heads: mu = fused @ mu_w + mu_b ; logvar = fused @ lv_w + lv_b
// ---------------------------------------------------------------------------
__global__ void head_kernel(const float* __restrict__ fused,
                            const float* __restrict__ mu_w, const float* __restrict__ mu_b,
                            const float* __restrict__ lv_w, const float* __restrict__ lv_b,
                            float* __restrict__ mu_out, float* __restrict__ lv_out)
{
    __shared__ float sf[256];
    int g = blockIdx.x, t = threadIdx.x;
    sf[t]       = fused[(size_t)g * 256 + t];
    sf[t + 128] = fused[(size_t)g * 256 + 128 + t];
    __syncthreads();
    if (t < 112) {
        bool is_mu = (t < 56);
        int j = is_mu ? t : t - 56;
        const float* Wp = is_mu ? mu_w : lv_w;
        float acc = is_mu ? mu_b[j] : lv_b[j];
#pragma unroll 8
        for (int k = 0; k < 256; k++) acc += sf[k] * Wp[k * ZD + j];
        if (is_mu) mu_out[(size_t)g * ZD + j] = acc;
        else       lv_out[(size_t)g * ZD + j] = acc;
    }
}

// ---------------------------------------------------------------------------
extern "C" void kernel_launch(void* const* d_in, const int* in_sizes, int n_in,
                              void* d_out, int out_size)
{
    const float* tree_x      = (const float*)d_in[0];
    const int*   tree_ei     = (const int*)  d_in[1];
    const float* graph_x     = (const float*)d_in[2];
    const int*   graph_ei    = (const int*)  d_in[3];
    const int*   batch_tree  = (const int*)  d_in[4];
    const int*   batch_graph = (const int*)  d_in[5];
    const float* t_proj_w = (const float*)d_in[6];
    const float* t_proj_b = (const float*)d_in[7];
    const float* t_msg_w  = (const float*)d_in[8];
    const float* t_msg_b  = (const float*)d_in[9];
    const float* t_lin_w  = (const float*)d_in[10];
    const float* t_lin_b  = (const float*)d_in[11];
    const float* gr_proj_w = (const float*)d_in[12];
    const float* gr_proj_b = (const float*)d_in[13];
    const float* gr_msg_w  = (const float*)d_in[14];
    const float* gr_msg_b  = (const float*)d_in[15];
    const float* gr_lin_w  = (const float*)d_in[16];
    const float* gr_lin_b  = (const float*)d_in[17];
    const float* mu_w = (const float*)d_in[18];
    const float* mu_b = (const float*)d_in[19];
    const float* lv_w = (const float*)d_in[20];
    const float* lv_b = (const float*)d_in[21];
    float* out = (float*)d_out;

    const int n_tree  = in_sizes[0] / 64;
    const int e_tree  = in_sizes[1] / 2;
    const int n_graph = in_sizes[2] / 32;
    const int e_graph = in_sizes[3] / 2;

    float *h, *A, *B, *aggr, *sums, *cnt;
    cudaGetSymbolAddress((void**)&h,    g_h);
    cudaGetSymbolAddress((void**)&A,    g_A);
    cudaGetSymbolAddress((void**)&B,    g_B);
    cudaGetSymbolAddress((void**)&aggr, g_aggr);
    cudaGetSymbolAddress((void**)&sums, g_sums);
    cudaGetSymbolAddress((void**)&cnt,  g_cnt);

    float* fused = out + 2 * NGRAPHS * ZD;   // output layout: mu | logvar | fused

    auto encode = [&](const float* x, int n, int din, const int* ei, int E,
                      const int* batch, const float* pw, const float* pb,
                      const float* mw, const float* mb,
                      const float* lw, const float* lb, int colofs) {
        int gb = (n + 127) / 128;
        // input projection with relu
        gemm_tf32<<<gb, 256>>>(x, pw, pb, h, n, din, 1);
        for (int l = 0; l < 3; l++) {
            // A = h @ W_top + msg_b   (dst-side contribution, bias folded in)
            gemm_tf32<<<gb, 256>>>(h, mw + (size_t)l * 256 * 128, mb + l * 128, A, n, 128, 0);
            // B = h @ W_bot           (src-side contribution)
            gemm_tf32<<<gb, 256>>>(h, mw + (size_t)l * 256 * 128 + 128 * 128, nullptr, B, n, 128, 0);
            cudaMemsetAsync(aggr, 0, (size_t)n * 128 * sizeof(float));
            int eb = (int)(((long long)E * 32 + 255) / 256);
            edge_agg<<<eb, 256>>>(ei, E, A, B, aggr);
            // h = relu(aggr @ lin_w + lin_b)
            gemm_tf32<<<gb, 256>>>(aggr, lw + (size_t)l * 128 * 128, lb + l * 128, h, n, 128, 1);
        }
        cudaMemsetAsync(sums, 0, (size_t)NGRAPHS * 128 * sizeof(float));
        cudaMemsetAsync(cnt,  0, (size_t)NGRAPHS * sizeof(float));
        int pbk = (int)(((long long)n * 32 + 255) / 256);
        pool_sum<<<pbk, 256>>>(h, batch, n, sums, cnt);
        pool_div<<<NGRAPHS, 128>>>(sums, cnt, fused, colofs);
    };

    encode(tree_x,  n_tree,  64, tree_ei,  e_tree,  batch_tree,
           t_proj_w, t_proj_b, t_msg_w, t_msg_b, t_lin_w, t_lin_b, 0);
    encode(graph_x, n_graph, 32, graph_ei, e_graph, batch_graph,
           gr_proj_w, gr_proj_b, gr_msg_w, gr_msg_b, gr_lin_w, gr_lin_b, 128);

    head_kernel<<<NGRAPHS, 128>>>(fused, mu_w, mu_b, lv_w, lv_b,
                                  out, out + NGRAPHS * ZD);
}

// round 3
// speedup vs baseline: 2.0795x; 1.1158x over previous
#include <cuda_runtime.h>
#include <cstdint>

#define HID 128
#define NGRAPHS 1024
#define ZD 56

// Scratch
__device__ float g_h   [100000 * 128];
__device__ float g_A   [100000 * 128];
__device__ float g_B   [100000 * 128];
__device__ float g_aggr[100000 * 128];
__device__ float g_sums[NGRAPHS * 128];
__device__ float g_cnt [NGRAPHS];
__device__ int   g_rowptr[100001];
__device__ int   g_cursor[100001];
__device__ int   g_csrsrc[400000];
__device__ int   g_bsums[128];

__device__ __forceinline__ uint32_t f2tf32(float v) {
    uint32_t t;
    asm("cvt.rna.tf32.f32 %0, %1;" : "=r"(t) : "f"(v));
    return t;
}

// ---------------------------------------------------------------------------
// Y[M,128] = act(X[M,K] @ W[K,128] + bias). tf32 MMA, 128x128 tile, 8 warps.
// If batch != null: instead of storing Y, scatter-add (mean-pool numerator)
// into sums[batch[row]*128 + col] via red.global (relu applied).
// ---------------------------------------------------------------------------
__global__ __launch_bounds__(256, 2)
void gemm_tf32(const float* __restrict__ X, const float* __restrict__ W,
               const float* __restrict__ bias, float* __restrict__ Y,
               int M, int K, int do_relu,
               const int* __restrict__ batch, float* __restrict__ sums)
{
    __shared__ uint32_t sX[128 * 36];
    __shared__ uint32_t sW[32 * 136];
    const int tid  = threadIdx.x;
    const int warp = tid >> 5, lane = tid & 31;
    const int g  = lane >> 2;
    const int tg = lane & 3;
    const int wm = (warp >> 1) * 32;
    const int wn = (warp & 1) * 64;
    const int row0 = blockIdx.x * 128;

    float c[2][8][4];
#pragma unroll
    for (int mi = 0; mi < 2; mi++)
#pragma unroll
        for (int ni = 0; ni < 8; ni++)
#pragma unroll
            for (int q = 0; q < 4; q++) c[mi][ni][q] = 0.0f;

    for (int k0 = 0; k0 < K; k0 += 32) {
#pragma unroll
        for (int i = tid; i < 128 * 32; i += 256) {
            int r = i >> 5, k = i & 31;
            int row = row0 + r;
            float v = (row < M) ? X[(size_t)row * K + k0 + k] : 0.0f;
            sX[r * 36 + k] = f2tf32(v);
        }
#pragma unroll
        for (int i = tid; i < 32 * 128; i += 256) {
            int kk = i >> 7, n = i & 127;
            sW[kk * 136 + n] = f2tf32(W[(size_t)(k0 + kk) * 128 + n]);
        }
        __syncthreads();

#pragma unroll
        for (int kk = 0; kk < 32; kk += 8) {
            uint32_t a[2][4], b[8][2];
#pragma unroll
            for (int mi = 0; mi < 2; mi++) {
                int r = wm + mi * 16 + g;
                a[mi][0] = sX[r * 36 + kk + tg];
                a[mi][1] = sX[(r + 8) * 36 + kk + tg];
                a[mi][2] = sX[r * 36 + kk + tg + 4];
                a[mi][3] = sX[(r + 8) * 36 + kk + tg + 4];
            }
#pragma unroll
            for (int ni = 0; ni < 8; ni++) {
                int n = wn + ni * 8 + g;
                b[ni][0] = sW[(kk + tg) * 136 + n];
                b[ni][1] = sW[(kk + tg + 4) * 136 + n];
            }
#pragma unroll
            for (int mi = 0; mi < 2; mi++)
#pragma unroll
                for (int ni = 0; ni < 8; ni++) {
                    asm volatile(
                        "mma.sync.aligned.m16n8k8.row.col.f32.tf32.tf32.f32 "
                        "{%0,%1,%2,%3},{%4,%5,%6,%7},{%8,%9},{%0,%1,%2,%3};"
                        : "+f"(c[mi][ni][0]), "+f"(c[mi][ni][1]),
                          "+f"(c[mi][ni][2]), "+f"(c[mi][ni][3])
                        : "r"(a[mi][0]), "r"(a[mi][1]), "r"(a[mi][2]), "r"(a[mi][3]),
                          "r"(b[ni][0]), "r"(b[ni][1]));
                }
        }
        __syncthreads();
    }

#pragma unroll
    for (int mi = 0; mi < 2; mi++) {
#pragma unroll
        for (int half = 0; half < 2; half++) {
            int row = row0 + wm + mi * 16 + g + half * 8;
            if (row < M) {
                int gsel = batch ? __ldg(batch + row) : 0;
#pragma unroll
                for (int ni = 0; ni < 8; ni++) {
                    int col = wn + ni * 8 + tg * 2;
                    float2 o;
                    o.x = c[mi][ni][half * 2 + 0];
                    o.y = c[mi][ni][half * 2 + 1];
                    if (bias) { o.x += bias[col]; o.y += bias[col + 1]; }
                    if (do_relu) { o.x = fmaxf(o.x, 0.f); o.y = fmaxf(o.y, 0.f); }
                    if (batch) {
                        float* p = sums + (size_t)gsel * 128 + col;
                        asm volatile("red.global.add.v2.f32 [%0], {%1,%2};"
                                     :: "l"(p), "f"(o.x), "f"(o.y) : "memory");
                    } else {
                        *(float2*)(Y + (size_t)row * 128 + col) = o;
                    }
                }
            }
        }
    }
}

// ---------------------------------------------------------------------------
// CSR build: counts -> exclusive scan -> fill
// ---------------------------------------------------------------------------
__global__ void k_count(const int* __restrict__ ei, int E, int* __restrict__ cnt)
{
    int i = blockIdx.x * blockDim.x + threadIdx.x;
    if (i < E) atomicAdd(cnt + __ldg(ei + E + i), 1);
}

__global__ void scan_block(int* __restrict__ data, int n, int* __restrict__ bsums)
{
    __shared__ int s[1024];
    int t = threadIdx.x;
    int i = blockIdx.x * 1024 + t;
    int v = (i < n) ? data[i] : 0;
    s[t] = v; __syncthreads();
    for (int d = 1; d < 1024; d <<= 1) {
        int x = (t >= d) ? s[t - d] : 0;
        __syncthreads();
        s[t] += x;
        __syncthreads();
    }
    if (i < n) data[i] = s[t] - v;           // exclusive
    if (t == 1023) bsums[blockIdx.x] = s[1023];
}

__global__ void scan_tops(int* __restrict__ bsums, int nb)
{
    __shared__ int s[128];
    int t = threadIdx.x;
    int v = (t < nb) ? bsums[t] : 0;
    s[t] = v; __syncthreads();
    for (int d = 1; d < 128; d <<= 1) {
        int x = (t >= d) ? s[t - d] : 0;
        __syncthreads();
        s[t] += x;
        __syncthreads();
    }
    if (t < nb) bsums[t] = s[t] - v;         // exclusive
}

__global__ void scan_add(int* __restrict__ data, int n,
                         const int* __restrict__ bsums, int total)
{
    int i = blockIdx.x * 1024 + threadIdx.x;
    if (i < n) data[i] += bsums[blockIdx.x];
    if (i == 0) data[n] = total;
}

__global__ void k_fill(const int* __restrict__ ei, int E,
                       int* __restrict__ cursor, int* __restrict__ csrsrc)
{
    int i = blockIdx.x * blockDim.x + threadIdx.x;
    if (i < E) {
        int d = __ldg(ei + E + i);
        int s = __ldg(ei + i);
        int p = atomicAdd(cursor + d, 1);
        csrsrc[p] = s;
    }
}

// ---------------------------------------------------------------------------
// aggr[i] = sum over edges (src->i) of relu(A[i] + B[src]).  Warp per node.
// ---------------------------------------------------------------------------
__global__ void csr_agg(const int* __restrict__ rowptr, const int* __restrict__ csrsrc,
                        const float* __restrict__ A, const float* __restrict__ B,
                        float* __restrict__ aggr, int n)
{
    int w = (blockIdx.x * blockDim.x + threadIdx.x) >> 5;
    int lane = threadIdx.x & 31;
    if (w >= n) return;
    int s0 = __ldg(rowptr + w), s1 = __ldg(rowptr + w + 1);
    float4 a = *(const float4*)(A + (size_t)w * 128 + lane * 4);
    float4 acc = make_float4(0.f, 0.f, 0.f, 0.f);
    for (int e = s0; e < s1; e++) {
        int s = __ldg(csrsrc + e);
        float4 b = *(const float4*)(B + (size_t)s * 128 + lane * 4);
        acc.x += fmaxf(a.x + b.x, 0.f);
        acc.y += fmaxf(a.y + b.y, 0.f);
        acc.z += fmaxf(a.z + b.z, 0.f);
        acc.w += fmaxf(a.w + b.w, 0.f);
    }
    *(float4*)(aggr + (size_t)w * 128 + lane * 4) = acc;
}

// ---------------------------------------------------------------------------
__global__ void pool_cnt(const int* __restrict__ batch, int n, float* __restrict__ cnt)
{
    int i = blockIdx.x * blockDim.x + threadIdx.x;
    if (i < n) atomicAdd(cnt + __ldg(batch + i), 1.0f);
}

__global__ void pool_div(const float* __restrict__ sums, const float* __restrict__ cnt,
                         float* __restrict__ fused, int colofs)
{
    int g = blockIdx.x, c = threadIdx.x;
    float cc = fmaxf(cnt[g], 1.0f);
    fused[(size_t)g * 256 + colofs + c] = sums[(size_t)g * 128 + c] / cc;
}

__global__ void head_kernel(const float* __restrict__ fused,
                            const float* __restrict__ mu_w, const float* __restrict__ mu_b,
                            const float* __restrict__ lv_w, const float* __restrict__ lv_b,
                            float* __restrict__ mu_out, float* __restrict__ lv_out)
{
    __shared__ float sf[256];
    int g = blockIdx.x, t = threadIdx.x;
    sf[t]       = fused[(size_t)g * 256 + t];
    sf[t + 128] = fused[(size_t)g * 256 + 128 + t];
    __syncthreads();
    if (t < 112) {
        bool is_mu = (t < 56);
        int j = is_mu ? t : t - 56;
        const float* Wp = is_mu ? mu_w : lv_w;
        float acc = is_mu ? mu_b[j] : lv_b[j];
#pragma unroll 8
        for (int k = 0; k < 256; k++) acc += sf[k] * Wp[k * ZD + j];
        if (is_mu) mu_out[(size_t)g * ZD + j] = acc;
        else       lv_out[(size_t)g * ZD + j] = acc;
    }
}

// ---------------------------------------------------------------------------
extern "C" void kernel_launch(void* const* d_in, const int* in_sizes, int n_in,
                              void* d_out, int out_size)
{
    const float* tree_x      = (const float*)d_in[0];
    const int*   tree_ei     = (const int*)  d_in[1];
    const float* graph_x     = (const float*)d_in[2];
    const int*   graph_ei    = (const int*)  d_in[3];
    const int*   batch_tree  = (const int*)  d_in[4];
    const int*   batch_graph = (const int*)  d_in[5];
    const float* t_proj_w = (const float*)d_in[6];
    const float* t_proj_b = (const float*)d_in[7];
    const float* t_msg_w  = (const float*)d_in[8];
    const float* t_msg_b  = (const float*)d_in[9];
    const float* t_lin_w  = (const float*)d_in[10];
    const float* t_lin_b  = (const float*)d_in[11];
    const float* gr_proj_w = (const float*)d_in[12];
    const float* gr_proj_b = (const float*)d_in[13];
    const float* gr_msg_w  = (const float*)d_in[14];
    const float* gr_msg_b  = (const float*)d_in[15];
    const float* gr_lin_w  = (const float*)d_in[16];
    const float* gr_lin_b  = (const float*)d_in[17];
    const float* mu_w = (const float*)d_in[18];
    const float* mu_b = (const float*)d_in[19];
    const float* lv_w = (const float*)d_in[20];
    const float* lv_b = (const float*)d_in[21];
    float* out = (float*)d_out;

    const int n_tree  = in_sizes[0] / 64;
    const int e_tree  = in_sizes[1] / 2;
    const int n_graph = in_sizes[2] / 32;
    const int e_graph = in_sizes[3] / 2;

    float *h, *A, *B, *aggr, *sums, *cnt;
    int *rowptr, *cursor, *csrsrc, *bsums;
    cudaGetSymbolAddress((void**)&h,      g_h);
    cudaGetSymbolAddress((void**)&A,      g_A);
    cudaGetSymbolAddress((void**)&B,      g_B);
    cudaGetSymbolAddress((void**)&aggr,   g_aggr);
    cudaGetSymbolAddress((void**)&sums,   g_sums);
    cudaGetSymbolAddress((void**)&cnt,    g_cnt);
    cudaGetSymbolAddress((void**)&rowptr, g_rowptr);
    cudaGetSymbolAddress((void**)&cursor, g_cursor);
    cudaGetSymbolAddress((void**)&csrsrc, g_csrsrc);
    cudaGetSymbolAddress((void**)&bsums,  g_bsums);

    float* fused = out + 2 * NGRAPHS * ZD;   // output layout: mu | logvar | fused

    auto encode = [&](const float* x, int n, int din, const int* ei, int E,
                      const int* batch, const float* pw, const float* pb,
                      const float* mw, const float* mb,
                      const float* lw, const float* lb, int colofs) {
        int gb  = (n + 127) / 128;
        int nb  = (n + 1023) / 1024;
        int ebk = (E + 255) / 256;
        int wbk = (int)(((long long)n * 32 + 255) / 256);

        // ---- CSR build (once per encoder, reused across layers) ----
        cudaMemsetAsync(rowptr, 0, (size_t)(n + 1) * sizeof(int));
        k_count<<<ebk, 256>>>(ei, E, rowptr);
        scan_block<<<nb, 1024>>>(rowptr, n, bsums);
        scan_tops<<<1, 128>>>(bsums, nb);
        scan_add<<<nb, 1024>>>(rowptr, n, bsums, E);
        cudaMemcpyAsync(cursor, rowptr, (size_t)n * sizeof(int),
                        cudaMemcpyDeviceToDevice);
        k_fill<<<ebk, 256>>>(ei, E, cursor, csrsrc);

        // ---- input projection ----
        gemm_tf32<<<gb, 256>>>(x, pw, pb, h, n, din, 1, nullptr, nullptr);

        for (int l = 0; l < 3; l++) {
            gemm_tf32<<<gb, 256>>>(h, mw + (size_t)l * 256 * 128, mb + l * 128,
                                   A, n, 128, 0, nullptr, nullptr);
            gemm_tf32<<<gb, 256>>>(h, mw + (size_t)l * 256 * 128 + 128 * 128, nullptr,
                                   B, n, 128, 0, nullptr, nullptr);
            csr_agg<<<wbk, 256>>>(rowptr, csrsrc, A, B, aggr, n);
            if (l < 2) {
                gemm_tf32<<<gb, 256>>>(aggr, lw + (size_t)l * 128 * 128, lb + l * 128,
                                       h, n, 128, 1, nullptr, nullptr);
            } else {
                // final layer: fuse relu + mean-pool numerator into epilogue
                cudaMemsetAsync(sums, 0, (size_t)NGRAPHS * 128 * sizeof(float));
                gemm_tf32<<<gb, 256>>>(aggr, lw + (size_t)l * 128 * 128, lb + l * 128,
                                       nullptr, n, 128, 1, batch, sums);
            }
        }
        cudaMemsetAsync(cnt, 0, (size_t)NGRAPHS * sizeof(float));
        pool_cnt<<<(n + 255) / 256, 256>>>(batch, n, cnt);
        pool_div<<<NGRAPHS, 128>>>(sums, cnt, fused, colofs);
    };

    encode(tree_x,  n_tree,  64, tree_ei,  e_tree,  batch_tree,
           t_proj_w, t_proj_b, t_msg_w, t_msg_b, t_lin_w, t_lin_b, 0);
    encode(graph_x, n_graph, 32, graph_ei, e_graph, batch_graph,
           gr_proj_w, gr_proj_b, gr_msg_w, gr_msg_b, gr_lin_w, gr_lin_b, 128);

    head_kernel<<<NGRAPHS, 128>>>(fused, mu_w, mu_b, lv_w, lv_b,
                                  out, out + NGRAPHS * ZD);
}

// round 4
// speedup vs baseline: 2.6431x; 1.2710x over previous
#include <cuda_runtime.h>
#include <cstdint>

#define HID 128
#define NGRAPHS 1024
#define ZD 56

// Scratch
__device__ float g_A   [100000 * 128];
__device__ float g_B   [100000 * 128];
__device__ float g_aggr[100000 * 128];
__device__ float g_sums[NGRAPHS * 128];
__device__ float g_cnt [NGRAPHS];
__device__ int   g_rowptr[100001];
__device__ int   g_cursor[100001];
__device__ int   g_csrsrc[400000];
__device__ int   g_bsums[128];

#define SH_STR 132
#define SW_STR 136

__device__ __forceinline__ uint32_t f2tf32(float v) {
    uint32_t t;
    asm("cvt.rna.tf32.f32 %0, %1;" : "=r"(t) : "f"(v));
    return t;
}

// One 32-k chunk of MMAs: A from sH (cols k0..k0+31), B from sW.
__device__ __forceinline__ void mma_chunk(float c[2][8][4],
                                          const uint32_t* __restrict__ sH, int k0,
                                          const uint32_t* __restrict__ sW,
                                          int wm, int wn, int g, int tg)
{
#pragma unroll
    for (int kk = 0; kk < 32; kk += 8) {
        uint32_t a[2][4], b[8][2];
#pragma unroll
        for (int mi = 0; mi < 2; mi++) {
            int r = wm + mi * 16 + g;
            a[mi][0] = sH[r * SH_STR + k0 + kk + tg];
            a[mi][1] = sH[(r + 8) * SH_STR + k0 + kk + tg];
            a[mi][2] = sH[r * SH_STR + k0 + kk + tg + 4];
            a[mi][3] = sH[(r + 8) * SH_STR + k0 + kk + tg + 4];
        }
#pragma unroll
        for (int ni = 0; ni < 8; ni++) {
            int n = wn + ni * 8 + g;
            b[ni][0] = sW[(kk + tg) * SW_STR + n];
            b[ni][1] = sW[(kk + tg + 4) * SW_STR + n];
        }
#pragma unroll
        for (int mi = 0; mi < 2; mi++)
#pragma unroll
            for (int ni = 0; ni < 8; ni++) {
                asm volatile(
                    "mma.sync.aligned.m16n8k8.row.col.f32.tf32.tf32.f32 "
                    "{%0,%1,%2,%3},{%4,%5,%6,%7},{%8,%9},{%0,%1,%2,%3};"
                    : "+f"(c[mi][ni][0]), "+f"(c[mi][ni][1]),
                      "+f"(c[mi][ni][2]), "+f"(c[mi][ni][3])
                    : "r"(a[mi][0]), "r"(a[mi][1]), "r"(a[mi][2]), "r"(a[mi][3]),
                      "r"(b[ni][0]), "r"(b[ni][1]));
            }
    }
}

// ---------------------------------------------------------------------------
// Fused node update:
//   h = relu(X[M,K] @ Wmain[K,128] + bmain)       (h kept in smem, tf32)
//   A = h @ Wtop + btop ;  B = h @ Wbot
// Block: 256 threads, 128-row tile, full 128-col width.
// ---------------------------------------------------------------------------
__global__ __launch_bounds__(256, 2)
void fused_layer(const float* __restrict__ X, int K, int M,
                 const float* __restrict__ Wmain, const float* __restrict__ bmain,
                 const float* __restrict__ Wtop,  const float* __restrict__ btop,
                 const float* __restrict__ Wbot,
                 float* __restrict__ Aout, float* __restrict__ Bout)
{
    __shared__ uint32_t sH[128 * SH_STR];   // X chunks, then h (tf32)
    __shared__ uint32_t sW[32 * SW_STR];
    const int tid  = threadIdx.x;
    const int warp = tid >> 5, lane = tid & 31;
    const int g  = lane >> 2;
    const int tg = lane & 3;
    const int wm = (warp >> 1) * 32;
    const int wn = (warp & 1) * 64;
    const int row0 = blockIdx.x * 128;

    float c[2][8][4];
#pragma unroll
    for (int mi = 0; mi < 2; mi++)
#pragma unroll
        for (int ni = 0; ni < 8; ni++)
#pragma unroll
            for (int q = 0; q < 4; q++) c[mi][ni][q] = 0.0f;

    // ---- phase 1: h accumulation ----
    for (int k0 = 0; k0 < K; k0 += 32) {
#pragma unroll
        for (int i = tid; i < 128 * 32; i += 256) {
            int r = i >> 5, k = i & 31;
            int row = row0 + r;
            float v = (row < M) ? X[(size_t)row * K + k0 + k] : 0.0f;
            sH[r * SH_STR + k0 + k] = f2tf32(v);
        }
#pragma unroll
        for (int i = tid; i < 32 * 128; i += 256) {
            int kk = i >> 7, n = i & 127;
            sW[kk * SW_STR + n] = f2tf32(Wmain[(size_t)(k0 + kk) * 128 + n]);
        }
        __syncthreads();
        mma_chunk(c, sH, k0, sW, wm, wn, g, tg);
        __syncthreads();
    }

    // ---- h = relu(c + bmain) -> sH (overwrite in place) ----
#pragma unroll
    for (int mi = 0; mi < 2; mi++)
#pragma unroll
        for (int half = 0; half < 2; half++) {
            int r = wm + mi * 16 + g + half * 8;   // local row
#pragma unroll
            for (int ni = 0; ni < 8; ni++) {
                int col = wn + ni * 8 + tg * 2;
                float vx = fmaxf(c[mi][ni][half * 2 + 0] + bmain[col],     0.f);
                float vy = fmaxf(c[mi][ni][half * 2 + 1] + bmain[col + 1], 0.f);
                sH[r * SH_STR + col]     = f2tf32(vx);
                sH[r * SH_STR + col + 1] = f2tf32(vy);
            }
        }
    __syncthreads();

    // ---- phase 2: A and B from h (K=128) ----
#pragma unroll 1
    for (int t = 0; t < 2; t++) {
        const float* Wp = t ? Wbot : Wtop;
        float* Yp = t ? Bout : Aout;
#pragma unroll
        for (int mi = 0; mi < 2; mi++)
#pragma unroll
            for (int ni = 0; ni < 8; ni++)
#pragma unroll
                for (int q = 0; q < 4; q++) c[mi][ni][q] = 0.0f;

#pragma unroll 1
        for (int k0 = 0; k0 < 128; k0 += 32) {
            __syncthreads();
#pragma unroll
            for (int i = tid; i < 32 * 128; i += 256) {
                int kk = i >> 7, n = i & 127;
                sW[kk * SW_STR + n] = f2tf32(Wp[(size_t)(k0 + kk) * 128 + n]);
            }
            __syncthreads();
            mma_chunk(c, sH, k0, sW, wm, wn, g, tg);
        }

#pragma unroll
        for (int mi = 0; mi < 2; mi++)
#pragma unroll
            for (int half = 0; half < 2; half++) {
                int row = row0 + wm + mi * 16 + g + half * 8;
                if (row < M) {
#pragma unroll
                    for (int ni = 0; ni < 8; ni++) {
                        int col = wn + ni * 8 + tg * 2;
                        float2 o;
                        o.x = c[mi][ni][half * 2 + 0];
                        o.y = c[mi][ni][half * 2 + 1];
                        if (t == 0) { o.x += btop[col]; o.y += btop[col + 1]; }
                        *(float2*)(Yp + (size_t)row * 128 + col) = o;
                    }
                }
            }
    }
}

// ---------------------------------------------------------------------------
// Final-layer GEMM with fused mean-pool numerator epilogue:
//   y = relu(X @ W + bias);  sums[batch[row]] += y
// ---------------------------------------------------------------------------
__global__ __launch_bounds__(256, 2)
void gemm_pool(const float* __restrict__ X, const float* __restrict__ W,
               const float* __restrict__ bias, int M,
               const int* __restrict__ batch, float* __restrict__ sums)
{
    __shared__ uint32_t sX[128 * 36];
    __shared__ uint32_t sW[32 * SW_STR];
    const int tid  = threadIdx.x;
    const int warp = tid >> 5, lane = tid & 31;
    const int g  = lane >> 2;
    const int tg = lane & 3;
    const int wm = (warp >> 1) * 32;
    const int wn = (warp & 1) * 64;
    const int row0 = blockIdx.x * 128;

    float c[2][8][4];
#pragma unroll
    for (int mi = 0; mi < 2; mi++)
#pragma unroll
        for (int ni = 0; ni < 8; ni++)
#pragma unroll
            for (int q = 0; q < 4; q++) c[mi][ni][q] = 0.0f;

    for (int k0 = 0; k0 < 128; k0 += 32) {
#pragma unroll
        for (int i = tid; i < 128 * 32; i += 256) {
            int r = i >> 5, k = i & 31;
            int row = row0 + r;
            float v = (row < M) ? X[(size_t)row * 128 + k0 + k] : 0.0f;
            sX[r * 36 + k] = f2tf32(v);
        }
#pragma unroll
        for (int i = tid; i < 32 * 128; i += 256) {
            int kk = i >> 7, n = i & 127;
            sW[kk * SW_STR + n] = f2tf32(W[(size_t)(k0 + kk) * 128 + n]);
        }
        __syncthreads();
#pragma unroll
        for (int kk = 0; kk < 32; kk += 8) {
            uint32_t a[2][4], b[8][2];
#pragma unroll
            for (int mi = 0; mi < 2; mi++) {
                int r = wm + mi * 16 + g;
                a[mi][0] = sX[r * 36 + kk + tg];
                a[mi][1] = sX[(r + 8) * 36 + kk + tg];
                a[mi][2] = sX[r * 36 + kk + tg + 4];
                a[mi][3] = sX[(r + 8) * 36 + kk + tg + 4];
            }
#pragma unroll
            for (int ni = 0; ni < 8; ni++) {
                int n = wn + ni * 8 + g;
                b[ni][0] = sW[(kk + tg) * SW_STR + n];
                b[ni][1] = sW[(kk + tg + 4) * SW_STR + n];
            }
#pragma unroll
            for (int mi = 0; mi < 2; mi++)
#pragma unroll
                for (int ni = 0; ni < 8; ni++) {
                    asm volatile(
                        "mma.sync.aligned.m16n8k8.row.col.f32.tf32.tf32.f32 "
                        "{%0,%1,%2,%3},{%4,%5,%6,%7},{%8,%9},{%0,%1,%2,%3};"
                        : "+f"(c[mi][ni][0]), "+f"(c[mi][ni][1]),
                          "+f"(c[mi][ni][2]), "+f"(c[mi][ni][3])
                        : "r"(a[mi][0]), "r"(a[mi][1]), "r"(a[mi][2]), "r"(a[mi][3]),
                          "r"(b[ni][0]), "r"(b[ni][1]));
                }
        }
        __syncthreads();
    }

#pragma unroll
    for (int mi = 0; mi < 2; mi++)
#pragma unroll
        for (int half = 0; half < 2; half++) {
            int row = row0 + wm + mi * 16 + g + half * 8;
            if (row < M) {
                int gsel = __ldg(batch + row);
#pragma unroll
                for (int ni = 0; ni < 8; ni++) {
                    int col = wn + ni * 8 + tg * 2;
                    float ox = fmaxf(c[mi][ni][half * 2 + 0] + bias[col],     0.f);
                    float oy = fmaxf(c[mi][ni][half * 2 + 1] + bias[col + 1], 0.f);
                    float* p = sums + (size_t)gsel * 128 + col;
                    asm volatile("red.global.add.v2.f32 [%0], {%1,%2};"
                                 :: "l"(p), "f"(ox), "f"(oy) : "memory");
                }
            }
        }
}

// ---------------------------------------------------------------------------
// CSR build: counts -> exclusive scan -> fill
// ---------------------------------------------------------------------------
__global__ void k_count(const int* __restrict__ ei, int E, int* __restrict__ cnt)
{
    int i = blockIdx.x * blockDim.x + threadIdx.x;
    if (i < E) atomicAdd(cnt + __ldg(ei + E + i), 1);
}

__global__ void scan_block(int* __restrict__ data, int n, int* __restrict__ bsums)
{
    __shared__ int s[1024];
    int t = threadIdx.x;
    int i = blockIdx.x * 1024 + t;
    int v = (i < n) ? data[i] : 0;
    s[t] = v; __syncthreads();
    for (int d = 1; d < 1024; d <<= 1) {
        int x = (t >= d) ? s[t - d] : 0;
        __syncthreads();
        s[t] += x;
        __syncthreads();
    }
    if (i < n) data[i] = s[t] - v;           // exclusive
    if (t == 1023) bsums[blockIdx.x] = s[1023];
}

__global__ void scan_tops(int* __restrict__ bsums, int nb)
{
    __shared__ int s[128];
    int t = threadIdx.x;
    int v = (t < nb) ? bsums[t] : 0;
    s[t] = v; __syncthreads();
    for (int d = 1; d < 128; d <<= 1) {
        int x = (t >= d) ? s[t - d] : 0;
        __syncthreads();
        s[t] += x;
        __syncthreads();
    }
    if (t < nb) bsums[t] = s[t] - v;         // exclusive
}

__global__ void scan_add(int* __restrict__ data, int n,
                         const int* __restrict__ bsums, int total)
{
    int i = blockIdx.x * 1024 + threadIdx.x;
    if (i < n) data[i] += bsums[blockIdx.x];
    if (i == 0) data[n] = total;
}

__global__ void k_fill(const int* __restrict__ ei, int E,
                       int* __restrict__ cursor, int* __restrict__ csrsrc)
{
    int i = blockIdx.x * blockDim.x + threadIdx.x;
    if (i < E) {
        int d = __ldg(ei + E + i);
        int s = __ldg(ei + i);
        int p = atomicAdd(cursor + d, 1);
        csrsrc[p] = s;
    }
}

// ---------------------------------------------------------------------------
// aggr[i] = sum over edges (src->i) of relu(A[i] + B[src]).  Warp per node.
// ---------------------------------------------------------------------------
__global__ void csr_agg(const int* __restrict__ rowptr, const int* __restrict__ csrsrc,
                        const float* __restrict__ A, const float* __restrict__ B,
                        float* __restrict__ aggr, int n)
{
    int w = (blockIdx.x * blockDim.x + threadIdx.x) >> 5;
    int lane = threadIdx.x & 31;
    if (w >= n) return;
    int s0 = __ldg(rowptr + w), s1 = __ldg(rowptr + w + 1);
    float4 a = *(const float4*)(A + (size_t)w * 128 + lane * 4);
    float4 acc = make_float4(0.f, 0.f, 0.f, 0.f);
    for (int e = s0; e < s1; e++) {
        int s = __ldg(csrsrc + e);
        float4 b = *(const float4*)(B + (size_t)s * 128 + lane * 4);
        acc.x += fmaxf(a.x + b.x, 0.f);
        acc.y += fmaxf(a.y + b.y, 0.f);
        acc.z += fmaxf(a.z + b.z, 0.f);
        acc.w += fmaxf(a.w + b.w, 0.f);
    }
    *(float4*)(aggr + (size_t)w * 128 + lane * 4) = acc;
}

// ---------------------------------------------------------------------------
__global__ void pool_cnt(const int* __restrict__ batch, int n, float* __restrict__ cnt)
{
    int i = blockIdx.x * blockDim.x + threadIdx.x;
    if (i < n) atomicAdd(cnt + __ldg(batch + i), 1.0f);
}

__global__ void pool_div(const float* __restrict__ sums, const float* __restrict__ cnt,
                         float* __restrict__ fused, int colofs)
{
    int g = blockIdx.x, c = threadIdx.x;
    float cc = fmaxf(cnt[g], 1.0f);
    fused[(size_t)g * 256 + colofs + c] = sums[(size_t)g * 128 + c] / cc;
}

__global__ void head_kernel(const float* __restrict__ fused,
                            const float* __restrict__ mu_w, const float* __restrict__ mu_b,
                            const float* __restrict__ lv_w, const float* __restrict__ lv_b,
                            float* __restrict__ mu_out, float* __restrict__ lv_out)
{
    __shared__ float sf[256];
    int g = blockIdx.x, t = threadIdx.x;
    sf[t]       = fused[(size_t)g * 256 + t];
    sf[t + 128] = fused[(size_t)g * 256 + 128 + t];
    __syncthreads();
    if (t < 112) {
        bool is_mu = (t < 56);
        int j = is_mu ? t : t - 56;
        const float* Wp = is_mu ? mu_w : lv_w;
        float acc = is_mu ? mu_b[j] : lv_b[j];
#pragma unroll 8
        for (int k = 0; k < 256; k++) acc += sf[k] * Wp[k * ZD + j];
        if (is_mu) mu_out[(size_t)g * ZD + j] = acc;
        else       lv_out[(size_t)g * ZD + j] = acc;
    }
}

// ---------------------------------------------------------------------------
extern "C" void kernel_launch(void* const* d_in, const int* in_sizes, int n_in,
                              void* d_out, int out_size)
{
    const float* tree_x      = (const float*)d_in[0];
    const int*   tree_ei     = (const int*)  d_in[1];
    const float* graph_x     = (const float*)d_in[2];
    const int*   graph_ei    = (const int*)  d_in[3];
    const int*   batch_tree  = (const int*)  d_in[4];
    const int*   batch_graph = (const int*)  d_in[5];
    const float* t_proj_w = (const float*)d_in[6];
    const float* t_proj_b = (const float*)d_in[7];
    const float* t_msg_w  = (const float*)d_in[8];
    const float* t_msg_b  = (const float*)d_in[9];
    const float* t_lin_w  = (const float*)d_in[10];
    const float* t_lin_b  = (const float*)d_in[11];
    const float* gr_proj_w = (const float*)d_in[12];
    const float* gr_proj_b = (const float*)d_in[13];
    const float* gr_msg_w  = (const float*)d_in[14];
    const float* gr_msg_b  = (const float*)d_in[15];
    const float* gr_lin_w  = (const float*)d_in[16];
    const float* gr_lin_b  = (const float*)d_in[17];
    const float* mu_w = (const float*)d_in[18];
    const float* mu_b = (const float*)d_in[19];
    const float* lv_w = (const float*)d_in[20];
    const float* lv_b = (const float*)d_in[21];
    float* out = (float*)d_out;

    const int n_tree  = in_sizes[0] / 64;
    const int e_tree  = in_sizes[1] / 2;
    const int n_graph = in_sizes[2] / 32;
    const int e_graph = in_sizes[3] / 2;

    float *A, *B, *aggr, *sums, *cnt;
    int *rowptr, *cursor, *csrsrc, *bsums;
    cudaGetSymbolAddress((void**)&A,      g_A);
    cudaGetSymbolAddress((void**)&B,      g_B);
    cudaGetSymbolAddress((void**)&aggr,   g_aggr);
    cudaGetSymbolAddress((void**)&sums,   g_sums);
    cudaGetSymbolAddress((void**)&cnt,    g_cnt);
    cudaGetSymbolAddress((void**)&rowptr, g_rowptr);
    cudaGetSymbolAddress((void**)&cursor, g_cursor);
    cudaGetSymbolAddress((void**)&csrsrc, g_csrsrc);
    cudaGetSymbolAddress((void**)&bsums,  g_bsums);

    float* fused = out + 2 * NGRAPHS * ZD;   // output layout: mu | logvar | fused

    auto encode = [&](const float* x, int n, int din, const int* ei, int E,
                      const int* batch, const float* pw, const float* pb,
                      const float* mw, const float* mb,
                      const float* lw, const float* lb, int colofs) {
        int gb  = (n + 127) / 128;
        int nb  = (n + 1023) / 1024;
        int ebk = (E + 255) / 256;
        int wbk = (int)(((long long)n * 32 + 255) / 256);

        // ---- CSR build (once per encoder, reused across layers) ----
        cudaMemsetAsync(rowptr, 0, (size_t)(n + 1) * sizeof(int));
        k_count<<<ebk, 256>>>(ei, E, rowptr);
        scan_block<<<nb, 1024>>>(rowptr, n, bsums);
        scan_tops<<<1, 128>>>(bsums, nb);
        scan_add<<<nb, 1024>>>(rowptr, n, bsums, E);
        cudaMemcpyAsync(cursor, rowptr, (size_t)n * sizeof(int),
                        cudaMemcpyDeviceToDevice);
        k_fill<<<ebk, 256>>>(ei, E, cursor, csrsrc);

        // ---- layer 0: proj + msg halves fused ----
        fused_layer<<<gb, 256>>>(x, din, n, pw, pb,
                                 mw, mb, mw + 128 * 128, A, B);
        csr_agg<<<wbk, 256>>>(rowptr, csrsrc, A, B, aggr, n);

        // ---- layers 1..2: lin + next msg halves fused ----
        for (int l = 1; l < 3; l++) {
            fused_layer<<<gb, 256>>>(aggr, 128, n,
                                     lw + (size_t)(l - 1) * 128 * 128, lb + (l - 1) * 128,
                                     mw + (size_t)l * 256 * 128, mb + l * 128,
                                     mw + (size_t)l * 256 * 128 + 128 * 128, A, B);
            csr_agg<<<wbk, 256>>>(rowptr, csrsrc, A, B, aggr, n);
        }

        // ---- final lin + mean-pool numerator ----
        cudaMemsetAsync(sums, 0, (size_t)NGRAPHS * 128 * sizeof(float));
        gemm_pool<<<gb, 256>>>(aggr, lw + (size_t)2 * 128 * 128, lb + 2 * 128,
                               n, batch, sums);
        cudaMemsetAsync(cnt, 0, (size_t)NGRAPHS * sizeof(float));
        pool_cnt<<<(n + 255) / 256, 256>>>(batch, n, cnt);
        pool_div<<<NGRAPHS, 128>>>(sums, cnt, fused, colofs);
    };

    encode(tree_x,  n_tree,  64, tree_ei,  e_tree,  batch_tree,
           t_proj_w, t_proj_b, t_msg_w, t_msg_b, t_lin_w, t_lin_b, 0);
    encode(graph_x, n_graph, 32, graph_ei, e_graph, batch_graph,
           gr_proj_w, gr_proj_b, gr_msg_w, gr_msg_b, gr_lin_w, gr_lin_b, 128);

    head_kernel<<<NGRAPHS, 128>>>(fused, mu_w, mu_b, lv_w, lv_b,
                                  out, out + NGRAPHS * ZD);
}

// round 5
// speedup vs baseline: 3.1372x; 1.1869x over previous
#include <cuda_runtime.h>
#include <cstdint>

#define HID 128
#define NGRAPHS 1024
#define ZD 56

// ---- graph-encoder scratch (100k nodes, 400k edges) ----
__device__ float g_A   [100000 * 128];
__device__ float g_B   [100000 * 128];
__device__ float g_aggr[100000 * 128];
__device__ float g_sums[NGRAPHS * 128];
__device__ float g_cnt [NGRAPHS];
__device__ int   g_rowptr[100001];
__device__ int   g_cursor[100001];
__device__ int   g_csrsrc[400000];
__device__ int   g_bsums[128];
// ---- tree-encoder scratch (20k nodes, 40k edges) ----
__device__ float t_A   [20000 * 128];
__device__ float t_B   [20000 * 128];
__device__ float t_aggr[20000 * 128];
__device__ float t_sums[NGRAPHS * 128];
__device__ float t_cnt [NGRAPHS];
__device__ int   t_rowptr[20001];
__device__ int   t_cursor[20001];
__device__ int   t_csrsrc[40000];
__device__ int   t_bsums[128];

#define SH_STR 132
#define SW_STR 136

__device__ __forceinline__ uint32_t f2tf32(float v) {
    uint32_t t;
    asm("cvt.rna.tf32.f32 %0, %1;" : "=r"(t) : "f"(v));
    return t;
}

__device__ __forceinline__ void mma_chunk(float c[2][8][4],
                                          const uint32_t* __restrict__ sH, int k0,
                                          const uint32_t* __restrict__ sW,
                                          int wm, int wn, int g, int tg)
{
#pragma unroll
    for (int kk = 0; kk < 32; kk += 8) {
        uint32_t a[2][4], b[8][2];
#pragma unroll
        for (int mi = 0; mi < 2; mi++) {
            int r = wm + mi * 16 + g;
            a[mi][0] = sH[r * SH_STR + k0 + kk + tg];
            a[mi][1] = sH[(r + 8) * SH_STR + k0 + kk + tg];
            a[mi][2] = sH[r * SH_STR + k0 + kk + tg + 4];
            a[mi][3] = sH[(r + 8) * SH_STR + k0 + kk + tg + 4];
        }
#pragma unroll
        for (int ni = 0; ni < 8; ni++) {
            int n = wn + ni * 8 + g;
            b[ni][0] = sW[(kk + tg) * SW_STR + n];
            b[ni][1] = sW[(kk + tg + 4) * SW_STR + n];
        }
#pragma unroll
        for (int mi = 0; mi < 2; mi++)
#pragma unroll
            for (int ni = 0; ni < 8; ni++) {
                asm volatile(
                    "mma.sync.aligned.m16n8k8.row.col.f32.tf32.tf32.f32 "
                    "{%0,%1,%2,%3},{%4,%5,%6,%7},{%8,%9},{%0,%1,%2,%3};"
                    : "+f"(c[mi][ni][0]), "+f"(c[mi][ni][1]),
                      "+f"(c[mi][ni][2]), "+f"(c[mi][ni][3])
                    : "r"(a[mi][0]), "r"(a[mi][1]), "r"(a[mi][2]), "r"(a[mi][3]),
                      "r"(b[ni][0]), "r"(b[ni][1]));
            }
    }
}

// ---------------------------------------------------------------------------
// Fused node update: h = relu(X@Wmain+b) kept in smem; A = h@Wtop+btop; B = h@Wbot
// ---------------------------------------------------------------------------
__global__ __launch_bounds__(256, 2)
void fused_layer(const float* __restrict__ X, int K, int M,
                 const float* __restrict__ Wmain, const float* __restrict__ bmain,
                 const float* __restrict__ Wtop,  const float* __restrict__ btop,
                 const float* __restrict__ Wbot,
                 float* __restrict__ Aout, float* __restrict__ Bout)
{
    __shared__ uint32_t sH[128 * SH_STR];
    __shared__ uint32_t sW[32 * SW_STR];
    const int tid  = threadIdx.x;
    const int warp = tid >> 5, lane = tid & 31;
    const int g  = lane >> 2;
    const int tg = lane & 3;
    const int wm = (warp >> 1) * 32;
    const int wn = (warp & 1) * 64;
    const int row0 = blockIdx.x * 128;

    float c[2][8][4];
#pragma unroll
    for (int mi = 0; mi < 2; mi++)
#pragma unroll
        for (int ni = 0; ni < 8; ni++)
#pragma unroll
            for (int q = 0; q < 4; q++) c[mi][ni][q] = 0.0f;

    for (int k0 = 0; k0 < K; k0 += 32) {
#pragma unroll
        for (int i = tid; i < 128 * 32; i += 256) {
            int r = i >> 5, k = i & 31;
            int row = row0 + r;
            float v = (row < M) ? X[(size_t)row * K + k0 + k] : 0.0f;
            sH[r * SH_STR + k0 + k] = f2tf32(v);
        }
#pragma unroll
        for (int i = tid; i < 32 * 128; i += 256) {
            int kk = i >> 7, n = i & 127;
            sW[kk * SW_STR + n] = f2tf32(Wmain[(size_t)(k0 + kk) * 128 + n]);
        }
        __syncthreads();
        mma_chunk(c, sH, k0, sW, wm, wn, g, tg);
        __syncthreads();
    }

#pragma unroll
    for (int mi = 0; mi < 2; mi++)
#pragma unroll
        for (int half = 0; half < 2; half++) {
            int r = wm + mi * 16 + g + half * 8;
#pragma unroll
            for (int ni = 0; ni < 8; ni++) {
                int col = wn + ni * 8 + tg * 2;
                float vx = fmaxf(c[mi][ni][half * 2 + 0] + bmain[col],     0.f);
                float vy = fmaxf(c[mi][ni][half * 2 + 1] + bmain[col + 1], 0.f);
                sH[r * SH_STR + col]     = f2tf32(vx);
                sH[r * SH_STR + col + 1] = f2tf32(vy);
            }
        }
    __syncthreads();

#pragma unroll 1
    for (int t = 0; t < 2; t++) {
        const float* Wp = t ? Wbot : Wtop;
        float* Yp = t ? Bout : Aout;
#pragma unroll
        for (int mi = 0; mi < 2; mi++)
#pragma unroll
            for (int ni = 0; ni < 8; ni++)
#pragma unroll
                for (int q = 0; q < 4; q++) c[mi][ni][q] = 0.0f;

#pragma unroll 1
        for (int k0 = 0; k0 < 128; k0 += 32) {
            __syncthreads();
#pragma unroll
            for (int i = tid; i < 32 * 128; i += 256) {
                int kk = i >> 7, n = i & 127;
                sW[kk * SW_STR + n] = f2tf32(Wp[(size_t)(k0 + kk) * 128 + n]);
            }
            __syncthreads();
            mma_chunk(c, sH, k0, sW, wm, wn, g, tg);
        }

#pragma unroll
        for (int mi = 0; mi < 2; mi++)
#pragma unroll
            for (int half = 0; half < 2; half++) {
                int row = row0 + wm + mi * 16 + g + half * 8;
                if (row < M) {
#pragma unroll
                    for (int ni = 0; ni < 8; ni++) {
                        int col = wn + ni * 8 + tg * 2;
                        float2 o;
                        o.x = c[mi][ni][half * 2 + 0];
                        o.y = c[mi][ni][half * 2 + 1];
                        if (t == 0) { o.x += btop[col]; o.y += btop[col + 1]; }
                        *(float2*)(Yp + (size_t)row * 128 + col) = o;
                    }
                }
            }
    }
}

// ---------------------------------------------------------------------------
// Final-layer GEMM with fused mean-pool numerator epilogue.
// ---------------------------------------------------------------------------
__global__ __launch_bounds__(256, 2)
void gemm_pool(const float* __restrict__ X, const float* __restrict__ W,
               const float* __restrict__ bias, int M,
               const int* __restrict__ batch, float* __restrict__ sums)
{
    __shared__ uint32_t sX[128 * 36];
    __shared__ uint32_t sW[32 * SW_STR];
    const int tid  = threadIdx.x;
    const int warp = tid >> 5, lane = tid & 31;
    const int g  = lane >> 2;
    const int tg = lane & 3;
    const int wm = (warp >> 1) * 32;
    const int wn = (warp & 1) * 64;
    const int row0 = blockIdx.x * 128;

    float c[2][8][4];
#pragma unroll
    for (int mi = 0; mi < 2; mi++)
#pragma unroll
        for (int ni = 0; ni < 8; ni++)
#pragma unroll
            for (int q = 0; q < 4; q++) c[mi][ni][q] = 0.0f;

    for (int k0 = 0; k0 < 128; k0 += 32) {
#pragma unroll
        for (int i = tid; i < 128 * 32; i += 256) {
            int r = i >> 5, k = i & 31;
            int row = row0 + r;
            float v = (row < M) ? X[(size_t)row * 128 + k0 + k] : 0.0f;
            sX[r * 36 + k] = f2tf32(v);
        }
#pragma unroll
        for (int i = tid; i < 32 * 128; i += 256) {
            int kk = i >> 7, n = i & 127;
            sW[kk * SW_STR + n] = f2tf32(W[(size_t)(k0 + kk) * 128 + n]);
        }
        __syncthreads();
#pragma unroll
        for (int kk = 0; kk < 32; kk += 8) {
            uint32_t a[2][4], b[8][2];
#pragma unroll
            for (int mi = 0; mi < 2; mi++) {
                int r = wm + mi * 16 + g;
                a[mi][0] = sX[r * 36 + kk + tg];
                a[mi][1] = sX[(r + 8) * 36 + kk + tg];
                a[mi][2] = sX[r * 36 + kk + tg + 4];
                a[mi][3] = sX[(r + 8) * 36 + kk + tg + 4];
            }
#pragma unroll
            for (int ni = 0; ni < 8; ni++) {
                int n = wn + ni * 8 + g;
                b[ni][0] = sW[(kk + tg) * SW_STR + n];
                b[ni][1] = sW[(kk + tg + 4) * SW_STR + n];
            }
#pragma unroll
            for (int mi = 0; mi < 2; mi++)
#pragma unroll
                for (int ni = 0; ni < 8; ni++) {
                    asm volatile(
                        "mma.sync.aligned.m16n8k8.row.col.f32.tf32.tf32.f32 "
                        "{%0,%1,%2,%3},{%4,%5,%6,%7},{%8,%9},{%0,%1,%2,%3};"
                        : "+f"(c[mi][ni][0]), "+f"(c[mi][ni][1]),
                          "+f"(c[mi][ni][2]), "+f"(c[mi][ni][3])
                        : "r"(a[mi][0]), "r"(a[mi][1]), "r"(a[mi][2]), "r"(a[mi][3]),
                          "r"(b[ni][0]), "r"(b[ni][1]));
                }
        }
        __syncthreads();
    }

#pragma unroll
    for (int mi = 0; mi < 2; mi++)
#pragma unroll
        for (int half = 0; half < 2; half++) {
            int row = row0 + wm + mi * 16 + g + half * 8;
            if (row < M) {
                int gsel = __ldg(batch + row);
#pragma unroll
                for (int ni = 0; ni < 8; ni++) {
                    int col = wn + ni * 8 + tg * 2;
                    float ox = fmaxf(c[mi][ni][half * 2 + 0] + bias[col],     0.f);
                    float oy = fmaxf(c[mi][ni][half * 2 + 1] + bias[col + 1], 0.f);
                    float* p = sums + (size_t)gsel * 128 + col;
                    asm volatile("red.global.add.v2.f32 [%0], {%1,%2};"
                                 :: "l"(p), "f"(ox), "f"(oy) : "memory");
                }
            }
        }
}

// ---------------------------------------------------------------------------
// CSR build
// ---------------------------------------------------------------------------
__global__ void k_count(const int* __restrict__ ei, int E, int* __restrict__ cnt)
{
    int i = blockIdx.x * blockDim.x + threadIdx.x;
    if (i < E) atomicAdd(cnt + __ldg(ei + E + i), 1);
}

__global__ void scan_block(int* __restrict__ data, int n, int* __restrict__ bsums)
{
    __shared__ int s[1024];
    int t = threadIdx.x;
    int i = blockIdx.x * 1024 + t;
    int v = (i < n) ? data[i] : 0;
    s[t] = v; __syncthreads();
    for (int d = 1; d < 1024; d <<= 1) {
        int x = (t >= d) ? s[t - d] : 0;
        __syncthreads();
        s[t] += x;
        __syncthreads();
    }
    if (i < n) data[i] = s[t] - v;
    if (t == 1023) bsums[blockIdx.x] = s[1023];
}

__global__ void scan_tops(int* __restrict__ bsums, int nb)
{
    __shared__ int s[128];
    int t = threadIdx.x;
    int v = (t < nb) ? bsums[t] : 0;
    s[t] = v; __syncthreads();
    for (int d = 1; d < 128; d <<= 1) {
        int x = (t >= d) ? s[t - d] : 0;
        __syncthreads();
        s[t] += x;
        __syncthreads();
    }
    if (t < nb) bsums[t] = s[t] - v;
}

__global__ void scan_add(int* __restrict__ data, int n,
                         const int* __restrict__ bsums, int total)
{
    int i = blockIdx.x * 1024 + threadIdx.x;
    if (i < n) data[i] += bsums[blockIdx.x];
    if (i == 0) data[n] = total;
}

__global__ void k_fill(const int* __restrict__ ei, int E,
                       int* __restrict__ cursor, int* __restrict__ csrsrc)
{
    int i = blockIdx.x * blockDim.x + threadIdx.x;
    if (i < E) {
        int d = __ldg(ei + E + i);
        int s = __ldg(ei + i);
        int p = atomicAdd(cursor + d, 1);
        csrsrc[p] = s;
    }
}

// ---------------------------------------------------------------------------
__global__ void csr_agg(const int* __restrict__ rowptr, const int* __restrict__ csrsrc,
                        const float* __restrict__ A, const float* __restrict__ B,
                        float* __restrict__ aggr, int n)
{
    int w = (blockIdx.x * blockDim.x + threadIdx.x) >> 5;
    int lane = threadIdx.x & 31;
    if (w >= n) return;
    int s0 = __ldg(rowptr + w), s1 = __ldg(rowptr + w + 1);
    float4 a = *(const float4*)(A + (size_t)w * 128 + lane * 4);
    float4 acc = make_float4(0.f, 0.f, 0.f, 0.f);
    for (int e = s0; e < s1; e++) {
        int s = __ldg(csrsrc + e);
        float4 b = *(const float4*)(B + (size_t)s * 128 + lane * 4);
        acc.x += fmaxf(a.x + b.x, 0.f);
        acc.y += fmaxf(a.y + b.y, 0.f);
        acc.z += fmaxf(a.z + b.z, 0.f);
        acc.w += fmaxf(a.w + b.w, 0.f);
    }
    *(float4*)(aggr + (size_t)w * 128 + lane * 4) = acc;
}

// ---------------------------------------------------------------------------
__global__ void pool_cnt(const int* __restrict__ batch, int n, float* __restrict__ cnt)
{
    int i = blockIdx.x * blockDim.x + threadIdx.x;
    if (i < n) atomicAdd(cnt + __ldg(batch + i), 1.0f);
}

__global__ void pool_div(const float* __restrict__ sums, const float* __restrict__ cnt,
                         float* __restrict__ fused, int colofs)
{
    int g = blockIdx.x, c = threadIdx.x;
    float cc = fmaxf(cnt[g], 1.0f);
    fused[(size_t)g * 256 + colofs + c] = sums[(size_t)g * 128 + c] / cc;
}

__global__ void head_kernel(const float* __restrict__ fused,
                            const float* __restrict__ mu_w, const float* __restrict__ mu_b,
                            const float* __restrict__ lv_w, const float* __restrict__ lv_b,
                            float* __restrict__ mu_out, float* __restrict__ lv_out)
{
    __shared__ float sf[256];
    int g = blockIdx.x, t = threadIdx.x;
    sf[t]       = fused[(size_t)g * 256 + t];
    sf[t + 128] = fused[(size_t)g * 256 + 128 + t];
    __syncthreads();
    if (t < 112) {
        bool is_mu = (t < 56);
        int j = is_mu ? t : t - 56;
        const float* Wp = is_mu ? mu_w : lv_w;
        float acc = is_mu ? mu_b[j] : lv_b[j];
#pragma unroll 8
        for (int k = 0; k < 256; k++) acc += sf[k] * Wp[k * ZD + j];
        if (is_mu) mu_out[(size_t)g * ZD + j] = acc;
        else       lv_out[(size_t)g * ZD + j] = acc;
    }
}

// ---------------------------------------------------------------------------
struct Scratch {
    float *A, *B, *aggr, *sums, *cnt;
    int *rowptr, *cursor, *csrsrc, *bsums;
};

static void encode(cudaStream_t st, const Scratch& S,
                   const float* x, int n, int din, const int* ei, int E,
                   const int* batch, const float* pw, const float* pb,
                   const float* mw, const float* mb,
                   const float* lw, const float* lb,
                   float* fused, int colofs)
{
    int gb  = (n + 127) / 128;
    int nb  = (n + 1023) / 1024;
    int ebk = (E + 255) / 256;
    int wbk = (int)(((long long)n * 32 + 255) / 256);

    cudaMemsetAsync(S.rowptr, 0, (size_t)(n + 1) * sizeof(int), st);
    k_count<<<ebk, 256, 0, st>>>(ei, E, S.rowptr);
    scan_block<<<nb, 1024, 0, st>>>(S.rowptr, n, S.bsums);
    scan_tops<<<1, 128, 0, st>>>(S.bsums, nb);
    scan_add<<<nb, 1024, 0, st>>>(S.rowptr, n, S.bsums, E);
    cudaMemcpyAsync(S.cursor, S.rowptr, (size_t)n * sizeof(int),
                    cudaMemcpyDeviceToDevice, st);
    k_fill<<<ebk, 256, 0, st>>>(ei, E, S.cursor, S.csrsrc);

    fused_layer<<<gb, 256, 0, st>>>(x, din, n, pw, pb,
                                    mw, mb, mw + 128 * 128, S.A, S.B);
    csr_agg<<<wbk, 256, 0, st>>>(S.rowptr, S.csrsrc, S.A, S.B, S.aggr, n);

    for (int l = 1; l < 3; l++) {
        fused_layer<<<gb, 256, 0, st>>>(S.aggr, 128, n,
                                        lw + (size_t)(l - 1) * 128 * 128, lb + (l - 1) * 128,
                                        mw + (size_t)l * 256 * 128, mb + l * 128,
                                        mw + (size_t)l * 256 * 128 + 128 * 128, S.A, S.B);
        csr_agg<<<wbk, 256, 0, st>>>(S.rowptr, S.csrsrc, S.A, S.B, S.aggr, n);
    }

    cudaMemsetAsync(S.sums, 0, (size_t)NGRAPHS * 128 * sizeof(float), st);
    gemm_pool<<<gb, 256, 0, st>>>(S.aggr, lw + (size_t)2 * 128 * 128, lb + 2 * 128,
                                  n, batch, S.sums);
    cudaMemsetAsync(S.cnt, 0, (size_t)NGRAPHS * sizeof(float), st);
    pool_cnt<<<(n + 255) / 256, 256, 0, st>>>(batch, n, S.cnt);
    pool_div<<<NGRAPHS, 128, 0, st>>>(S.sums, S.cnt, fused, colofs);
}

extern "C" void kernel_launch(void* const* d_in, const int* in_sizes, int n_in,
                              void* d_out, int out_size)
{
    const float* tree_x      = (const float*)d_in[0];
    const int*   tree_ei     = (const int*)  d_in[1];
    const float* graph_x     = (const float*)d_in[2];
    const int*   graph_ei    = (const int*)  d_in[3];
    const int*   batch_tree  = (const int*)  d_in[4];
    const int*   batch_graph = (const int*)  d_in[5];
    const float* t_proj_w = (const float*)d_in[6];
    const float* t_proj_b = (const float*)d_in[7];
    const float* t_msg_w  = (const float*)d_in[8];
    const float* t_msg_b  = (const float*)d_in[9];
    const float* t_lin_w  = (const float*)d_in[10];
    const float* t_lin_b  = (const float*)d_in[11];
    const float* gr_proj_w = (const float*)d_in[12];
    const float* gr_proj_b = (const float*)d_in[13];
    const float* gr_msg_w  = (const float*)d_in[14];
    const float* gr_msg_b  = (const float*)d_in[15];
    const float* gr_lin_w  = (const float*)d_in[16];
    const float* gr_lin_b  = (const float*)d_in[17];
    const float* mu_w = (const float*)d_in[18];
    const float* mu_b = (const float*)d_in[19];
    const float* lv_w = (const float*)d_in[20];
    const float* lv_b = (const float*)d_in[21];
    float* out = (float*)d_out;

    const int n_tree  = in_sizes[0] / 64;
    const int e_tree  = in_sizes[1] / 2;
    const int n_graph = in_sizes[2] / 32;
    const int e_graph = in_sizes[3] / 2;

    Scratch G, T;
    cudaGetSymbolAddress((void**)&G.A,      g_A);
    cudaGetSymbolAddress((void**)&G.B,      g_B);
    cudaGetSymbolAddress((void**)&G.aggr,   g_aggr);
    cudaGetSymbolAddress((void**)&G.sums,   g_sums);
    cudaGetSymbolAddress((void**)&G.cnt,    g_cnt);
    cudaGetSymbolAddress((void**)&G.rowptr, g_rowptr);
    cudaGetSymbolAddress((void**)&G.cursor, g_cursor);
    cudaGetSymbolAddress((void**)&G.csrsrc, g_csrsrc);
    cudaGetSymbolAddress((void**)&G.bsums,  g_bsums);
    cudaGetSymbolAddress((void**)&T.A,      t_A);
    cudaGetSymbolAddress((void**)&T.B,      t_B);
    cudaGetSymbolAddress((void**)&T.aggr,   t_aggr);
    cudaGetSymbolAddress((void**)&T.sums,   t_sums);
    cudaGetSymbolAddress((void**)&T.cnt,    t_cnt);
    cudaGetSymbolAddress((void**)&T.rowptr, t_rowptr);
    cudaGetSymbolAddress((void**)&T.cursor, t_cursor);
    cudaGetSymbolAddress((void**)&T.csrsrc, t_csrsrc);
    cudaGetSymbolAddress((void**)&T.bsums,  t_bsums);

    // One-time host resources (no device memory involved).
    static cudaStream_t s_tree = nullptr;
    static cudaEvent_t ev_fork = nullptr, ev_join = nullptr;
    if (!s_tree) {
        cudaStreamCreateWithFlags(&s_tree, cudaStreamNonBlocking);
        cudaEventCreateWithFlags(&ev_fork, cudaEventDisableTiming);
        cudaEventCreateWithFlags(&ev_join, cudaEventDisableTiming);
    }

    float* fused = out + 2 * NGRAPHS * ZD;   // output layout: mu | logvar | fused

    // Fork: tree encoder on side stream, graph encoder on main stream.
    cudaEventRecord(ev_fork, 0);
    cudaStreamWaitEvent(s_tree, ev_fork, 0);

    encode(s_tree, T, tree_x, n_tree, 64, tree_ei, e_tree, batch_tree,
           t_proj_w, t_proj_b, t_msg_w, t_msg_b, t_lin_w, t_lin_b, fused, 0);
    encode(0, G, graph_x, n_graph, 32, graph_ei, e_graph, batch_graph,
           gr_proj_w, gr_proj_b, gr_msg_w, gr_msg_b, gr_lin_w, gr_lin_b, fused, 128);

    // Join
    cudaEventRecord(ev_join, s_tree);
    cudaStreamWaitEvent(0, ev_join, 0);

    head_kernel<<<NGRAPHS, 128>>>(fused, mu_w, mu_b, lv_w, lv_b,
                                  out, out + NGRAPHS * ZD);
}

// round 6
// speedup vs baseline: 3.3994x; 1.0836x over previous
#include <cuda_runtime.h>
#include <cstdint>

#define HID 128
#define NGRAPHS 1024
#define ZD 56

// ---- graph-encoder scratch ----
__device__ float g_A   [100000 * 128];
__device__ float g_B   [100000 * 128];
__device__ float g_aggr[100000 * 128];
__device__ float g_sums[NGRAPHS * 128];
__device__ float g_cnt [NGRAPHS];
__device__ int   g_rowptr[100001];
__device__ int   g_cursor[100001];
__device__ int   g_csrsrc[400000];
__device__ int   g_bsums[128];
__device__ float g_wt  [160000];
// ---- tree-encoder scratch ----
__device__ float t_A   [20000 * 128];
__device__ float t_B   [20000 * 128];
__device__ float t_aggr[20000 * 128];
__device__ float t_sums[NGRAPHS * 128];
__device__ float t_cnt [NGRAPHS];
__device__ int   t_rowptr[20001];
__device__ int   t_cursor[20001];
__device__ int   t_csrsrc[40000];
__device__ int   t_bsums[128];
__device__ float t_wt  [160000];

#define SH_STR 132
#define SW_STR 136

__device__ __forceinline__ uint32_t f2tf32(float v) {
    uint32_t t;
    asm("cvt.rna.tf32.f32 %0, %1;" : "=r"(t) : "f"(v));
    return t;
}

__device__ __forceinline__ uint32_t smem_u32(const void* p) {
    return (uint32_t)__cvta_generic_to_shared(p);
}
__device__ __forceinline__ void cp16(uint32_t dst, const void* src) {
    asm volatile("cp.async.cg.shared.global [%0], [%1], 16;" :: "r"(dst), "l"(src));
}
__device__ __forceinline__ void cp16z(uint32_t dst, const void* src, int srcsz) {
    asm volatile("cp.async.cg.shared.global [%0], [%1], 16, %2;"
                 :: "r"(dst), "l"(src), "r"(srcsz));
}
#define CP_COMMIT() asm volatile("cp.async.commit_group;")
template<int N> __device__ __forceinline__ void cp_wait() {
    asm volatile("cp.async.wait_group %0;" :: "n"(N));
}

__device__ __forceinline__ void mma_chunk(float c[2][8][4],
                                          const uint32_t* __restrict__ sH, int k0,
                                          const uint32_t* __restrict__ sW,
                                          int wm, int wn, int g, int tg)
{
#pragma unroll
    for (int kk = 0; kk < 32; kk += 8) {
        uint32_t a[2][4], b[8][2];
#pragma unroll
        for (int mi = 0; mi < 2; mi++) {
            int r = wm + mi * 16 + g;
            a[mi][0] = sH[r * SH_STR + k0 + kk + tg];
            a[mi][1] = sH[(r + 8) * SH_STR + k0 + kk + tg];
            a[mi][2] = sH[r * SH_STR + k0 + kk + tg + 4];
            a[mi][3] = sH[(r + 8) * SH_STR + k0 + kk + tg + 4];
        }
#pragma unroll
        for (int ni = 0; ni < 8; ni++) {
            int n = wn + ni * 8 + g;
            b[ni][0] = sW[(kk + tg) * SW_STR + n];
            b[ni][1] = sW[(kk + tg + 4) * SW_STR + n];
        }
#pragma unroll
        for (int mi = 0; mi < 2; mi++)
#pragma unroll
            for (int ni = 0; ni < 8; ni++) {
                asm volatile(
                    "mma.sync.aligned.m16n8k8.row.col.f32.tf32.tf32.f32 "
                    "{%0,%1,%2,%3},{%4,%5,%6,%7},{%8,%9},{%0,%1,%2,%3};"
                    : "+f"(c[mi][ni][0]), "+f"(c[mi][ni][1]),
                      "+f"(c[mi][ni][2]), "+f"(c[mi][ni][3])
                    : "r"(a[mi][0]), "r"(a[mi][1]), "r"(a[mi][2]), "r"(a[mi][3]),
                      "r"(b[ni][0]), "r"(b[ni][1]));
            }
    }
}

// ---------------------------------------------------------------------------
// Fused node update with cp.async weight pipeline.
// Weights pre-converted to tf32. X pre-converted unless xcvt=1 (layer 0).
// Chunk list: n1 = K/32 chunks of Wmain, then 4 of Wtop, 4 of Wbot.
// ---------------------------------------------------------------------------
__global__ __launch_bounds__(256, 2)
void fused_layer(const float* __restrict__ X, int K, int M, int xcvt,
                 const float* __restrict__ Wmain, const float* __restrict__ bmain,
                 const float* __restrict__ Wtop,  const float* __restrict__ btop,
                 const float* __restrict__ Wbot,
                 float* __restrict__ Aout, float* __restrict__ Bout)
{
    __shared__ uint32_t sH[128 * SH_STR];
    __shared__ uint32_t sW[2][32 * SW_STR];
    const int tid  = threadIdx.x;
    const int warp = tid >> 5, lane = tid & 31;
    const int g  = lane >> 2;
    const int tg = lane & 3;
    const int wm = (warp >> 1) * 32;
    const int wn = (warp & 1) * 64;
    const int row0 = blockIdx.x * 128;

    const int n1 = K >> 5;
    const int total = n1 + 8;

    auto wsrc = [&](int i) -> const float* {
        if (i < n1) return Wmain + (size_t)i * 4096;
        int j = i - n1;
        return (j < 4) ? (Wtop + (size_t)j * 4096) : (Wbot + (size_t)(j - 4) * 4096);
    };
    auto issue_w = [&](int i, int buf) {
        const float* src = wsrc(i);
        uint32_t base = smem_u32(&sW[buf][0]);
#pragma unroll
        for (int s = tid; s < 1024; s += 256) {
            int row = s >> 5, c4 = s & 31;
            cp16(base + (uint32_t)(row * SW_STR + c4 * 4) * 4, src + row * 128 + c4 * 4);
        }
    };

    // ---- prologue ----
    if (!xcvt) {   // K == 128, X already tf32: raw async copy of full tile
        uint32_t base = smem_u32(sH);
        for (int s = tid; s < 128 * 32; s += 256) {
            int row = s >> 5, c4 = s & 31;
            const float* src = X + (size_t)(row0 + row) * 128 + c4 * 4;
            cp16z(base + (uint32_t)(row * SH_STR + c4 * 4) * 4, src,
                  (row0 + row < M) ? 16 : 0);
        }
    }
    issue_w(0, 0); CP_COMMIT();
    issue_w(1, 1); CP_COMMIT();
    if (xcvt) {    // layer 0: convert raw input (K = 32 or 64)
        int ksh = (K == 32) ? 5 : 6;
        for (int i = tid; i < 128 * K; i += 256) {
            int r = i >> ksh, k = i & (K - 1);
            int row = row0 + r;
            float v = (row < M) ? X[(size_t)row * K + k] : 0.0f;
            sH[r * SH_STR + k] = f2tf32(v);
        }
    }

    float c[2][8][4];
#pragma unroll
    for (int mi = 0; mi < 2; mi++)
#pragma unroll
        for (int ni = 0; ni < 8; ni++)
#pragma unroll
            for (int q = 0; q < 4; q++) c[mi][ni][q] = 0.0f;

    for (int i = 0; i < total; i++) {
        if (i + 2 < total) cp_wait<1>(); else cp_wait<0>();
        __syncthreads();
        int k0 = (i < n1) ? (i << 5) : (((i - n1) & 3) << 5);
        mma_chunk(c, sH, k0, &sW[i & 1][0], wm, wn, g, tg);
        __syncthreads();
        if (i + 2 < total) { issue_w(i + 2, i & 1); CP_COMMIT(); }

        if (i == n1 - 1) {
            // h = relu(c + bmain) -> sH (tf32); reset c
#pragma unroll
            for (int mi = 0; mi < 2; mi++)
#pragma unroll
                for (int half = 0; half < 2; half++) {
                    int r = wm + mi * 16 + g + half * 8;
#pragma unroll
                    for (int ni = 0; ni < 8; ni++) {
                        int col = wn + ni * 8 + tg * 2;
                        float vx = fmaxf(c[mi][ni][half * 2 + 0] + bmain[col],     0.f);
                        float vy = fmaxf(c[mi][ni][half * 2 + 1] + bmain[col + 1], 0.f);
                        sH[r * SH_STR + col]     = f2tf32(vx);
                        sH[r * SH_STR + col + 1] = f2tf32(vy);
                    }
                }
#pragma unroll
            for (int mi = 0; mi < 2; mi++)
#pragma unroll
                for (int ni = 0; ni < 8; ni++)
#pragma unroll
                    for (int q = 0; q < 4; q++) c[mi][ni][q] = 0.0f;
        } else if (i == n1 + 3) {
            // store A = c + btop; reset c
#pragma unroll
            for (int mi = 0; mi < 2; mi++)
#pragma unroll
                for (int half = 0; half < 2; half++) {
                    int row = row0 + wm + mi * 16 + g + half * 8;
                    if (row < M) {
#pragma unroll
                        for (int ni = 0; ni < 8; ni++) {
                            int col = wn + ni * 8 + tg * 2;
                            float2 o;
                            o.x = c[mi][ni][half * 2 + 0] + btop[col];
                            o.y = c[mi][ni][half * 2 + 1] + btop[col + 1];
                            *(float2*)(Aout + (size_t)row * 128 + col) = o;
                        }
                    }
                }
#pragma unroll
            for (int mi = 0; mi < 2; mi++)
#pragma unroll
                for (int ni = 0; ni < 8; ni++)
#pragma unroll
                    for (int q = 0; q < 4; q++) c[mi][ni][q] = 0.0f;
        } else if (i == total - 1) {
            // store B = c
#pragma unroll
            for (int mi = 0; mi < 2; mi++)
#pragma unroll
                for (int half = 0; half < 2; half++) {
                    int row = row0 + wm + mi * 16 + g + half * 8;
                    if (row < M) {
#pragma unroll
                        for (int ni = 0; ni < 8; ni++) {
                            int col = wn + ni * 8 + tg * 2;
                            float2 o;
                            o.x = c[mi][ni][half * 2 + 0];
                            o.y = c[mi][ni][half * 2 + 1];
                            *(float2*)(Bout + (size_t)row * 128 + col) = o;
                        }
                    }
                }
        }
    }
}

// ---------------------------------------------------------------------------
// Final-layer GEMM with fused mean-pool numerator epilogue.
// ---------------------------------------------------------------------------
__global__ __launch_bounds__(256, 2)
void gemm_pool(const float* __restrict__ X, const float* __restrict__ W,
               const float* __restrict__ bias, int M,
               const int* __restrict__ batch, float* __restrict__ sums)
{
    __shared__ uint32_t sX[128 * 36];
    __shared__ uint32_t sW[32 * SW_STR];
    const int tid  = threadIdx.x;
    const int warp = tid >> 5, lane = tid & 31;
    const int g  = lane >> 2;
    const int tg = lane & 3;
    const int wm = (warp >> 1) * 32;
    const int wn = (warp & 1) * 64;
    const int row0 = blockIdx.x * 128;

    float c[2][8][4];
#pragma unroll
    for (int mi = 0; mi < 2; mi++)
#pragma unroll
        for (int ni = 0; ni < 8; ni++)
#pragma unroll
            for (int q = 0; q < 4; q++) c[mi][ni][q] = 0.0f;

    for (int k0 = 0; k0 < 128; k0 += 32) {
#pragma unroll
        for (int i = tid; i < 128 * 32; i += 256) {
            int r = i >> 5, k = i & 31;
            int row = row0 + r;
            float v = (row < M) ? X[(size_t)row * 128 + k0 + k] : 0.0f;
            sX[r * 36 + k] = f2tf32(v);
        }
#pragma unroll
        for (int i = tid; i < 32 * 128; i += 256) {
            int kk = i >> 7, n = i & 127;
            sW[kk * SW_STR + n] = f2tf32(W[(size_t)(k0 + kk) * 128 + n]);
        }
        __syncthreads();
#pragma unroll
        for (int kk = 0; kk < 32; kk += 8) {
            uint32_t a[2][4], b[8][2];
#pragma unroll
            for (int mi = 0; mi < 2; mi++) {
                int r = wm + mi * 16 + g;
                a[mi][0] = sX[r * 36 + kk + tg];
                a[mi][1] = sX[(r + 8) * 36 + kk + tg];
                a[mi][2] = sX[r * 36 + kk + tg + 4];
                a[mi][3] = sX[(r + 8) * 36 + kk + tg + 4];
            }
#pragma unroll
            for (int ni = 0; ni < 8; ni++) {
                int n = wn + ni * 8 + g;
                b[ni][0] = sW[(kk + tg) * SW_STR + n];
                b[ni][1] = sW[(kk + tg + 4) * SW_STR + n];
            }
#pragma unroll
            for (int mi = 0; mi < 2; mi++)
#pragma unroll
                for (int ni = 0; ni < 8; ni++) {
                    asm volatile(
                        "mma.sync.aligned.m16n8k8.row.col.f32.tf32.tf32.f32 "
                        "{%0,%1,%2,%3},{%4,%5,%6,%7},{%8,%9},{%0,%1,%2,%3};"
                        : "+f"(c[mi][ni][0]), "+f"(c[mi][ni][1]),
                          "+f"(c[mi][ni][2]), "+f"(c[mi][ni][3])
                        : "r"(a[mi][0]), "r"(a[mi][1]), "r"(a[mi][2]), "r"(a[mi][3]),
                          "r"(b[ni][0]), "r"(b[ni][1]));
                }
        }
        __syncthreads();
    }

#pragma unroll
    for (int mi = 0; mi < 2; mi++)
#pragma unroll
        for (int half = 0; half < 2; half++) {
            int row = row0 + wm + mi * 16 + g + half * 8;
            if (row < M) {
                int gsel = __ldg(batch + row);
#pragma unroll
                for (int ni = 0; ni < 8; ni++) {
                    int col = wn + ni * 8 + tg * 2;
                    float ox = fmaxf(c[mi][ni][half * 2 + 0] + bias[col],     0.f);
                    float oy = fmaxf(c[mi][ni][half * 2 + 1] + bias[col + 1], 0.f);
                    float* p = sums + (size_t)gsel * 128 + col;
                    asm volatile("red.global.add.v2.f32 [%0], {%1,%2};"
                                 :: "l"(p), "f"(ox), "f"(oy) : "memory");
                }
            }
        }
}

// ---------------------------------------------------------------------------
__global__ void k_cvt(const float* __restrict__ src, float* __restrict__ dst, int n)
{
    int i = blockIdx.x * blockDim.x + threadIdx.x;
    if (i < n) dst[i] = __uint_as_float(f2tf32(src[i]));
}

// ---------------------------------------------------------------------------
// CSR build
// ---------------------------------------------------------------------------
__global__ void k_count(const int* __restrict__ ei, int E, int* __restrict__ cnt)
{
    int i = blockIdx.x * blockDim.x + threadIdx.x;
    if (i < E) atomicAdd(cnt + __ldg(ei + E + i), 1);
}

__global__ void scan_block(int* __restrict__ data, int n, int* __restrict__ bsums)
{
    __shared__ int s[1024];
    int t = threadIdx.x;
    int i = blockIdx.x * 1024 + t;
    int v = (i < n) ? data[i] : 0;
    s[t] = v; __syncthreads();
    for (int d = 1; d < 1024; d <<= 1) {
        int x = (t >= d) ? s[t - d] : 0;
        __syncthreads();
        s[t] += x;
        __syncthreads();
    }
    if (i < n) data[i] = s[t] - v;
    if (t == 1023) bsums[blockIdx.x] = s[1023];
}

__global__ void scan_tops(int* __restrict__ bsums, int nb)
{
    __shared__ int s[128];
    int t = threadIdx.x;
    int v = (t < nb) ? bsums[t] : 0;
    s[t] = v; __syncthreads();
    for (int d = 1; d < 128; d <<= 1) {
        int x = (t >= d) ? s[t - d] : 0;
        __syncthreads();
        s[t] += x;
        __syncthreads();
    }
    if (t < nb) bsums[t] = s[t] - v;
}

__global__ void scan_add(int* __restrict__ data, int n,
                         const int* __restrict__ bsums, int total)
{
    int i = blockIdx.x * 1024 + threadIdx.x;
    if (i < n) data[i] += bsums[blockIdx.x];
    if (i == 0) data[n] = total;
}

__global__ void k_fill(const int* __restrict__ ei, int E,
                       int* __restrict__ cursor, int* __restrict__ csrsrc)
{
    int i = blockIdx.x * blockDim.x + threadIdx.x;
    if (i < E) {
        int d = __ldg(ei + E + i);
        int s = __ldg(ei + i);
        int p = atomicAdd(cursor + d, 1);
        csrsrc[p] = s;
    }
}

// ---------------------------------------------------------------------------
// aggr[i] = sum_e relu(A[i] + B[src_e]); output pre-rounded to tf32 so the
// consuming GEMMs can raw-copy (numerically identical to cvt at staging).
// ---------------------------------------------------------------------------
__global__ void csr_agg(const int* __restrict__ rowptr, const int* __restrict__ csrsrc,
                        const float* __restrict__ A, const float* __restrict__ B,
                        float* __restrict__ aggr, int n)
{
    int w = (blockIdx.x * blockDim.x + threadIdx.x) >> 5;
    int lane = threadIdx.x & 31;
    if (w >= n) return;
    int s0 = __ldg(rowptr + w), s1 = __ldg(rowptr + w + 1);
    float4 a = *(const float4*)(A + (size_t)w * 128 + lane * 4);
    float4 acc = make_float4(0.f, 0.f, 0.f, 0.f);
    for (int e = s0; e < s1; e++) {
        int s = __ldg(csrsrc + e);
        float4 b = *(const float4*)(B + (size_t)s * 128 + lane * 4);
        acc.x += fmaxf(a.x + b.x, 0.f);
        acc.y += fmaxf(a.y + b.y, 0.f);
        acc.z += fmaxf(a.z + b.z, 0.f);
        acc.w += fmaxf(a.w + b.w, 0.f);
    }
    float4 o;
    o.x = __uint_as_float(f2tf32(acc.x));
    o.y = __uint_as_float(f2tf32(acc.y));
    o.z = __uint_as_float(f2tf32(acc.z));
    o.w = __uint_as_float(f2tf32(acc.w));
    *(float4*)(aggr + (size_t)w * 128 + lane * 4) = o;
}

// ---------------------------------------------------------------------------
__global__ void pool_cnt(const int* __restrict__ batch, int n, float* __restrict__ cnt)
{
    int i = blockIdx.x * blockDim.x + threadIdx.x;
    if (i < n) atomicAdd(cnt + __ldg(batch + i), 1.0f);
}

__global__ void pool_div(const float* __restrict__ sums, const float* __restrict__ cnt,
                         float* __restrict__ fused, int colofs)
{
    int g = blockIdx.x, c = threadIdx.x;
    float cc = fmaxf(cnt[g], 1.0f);
    fused[(size_t)g * 256 + colofs + c] = sums[(size_t)g * 128 + c] / cc;
}

__global__ void head_kernel(const float* __restrict__ fused,
                            const float* __restrict__ mu_w, const float* __restrict__ mu_b,
                            const float* __restrict__ lv_w, const float* __restrict__ lv_b,
                            float* __restrict__ mu_out, float* __restrict__ lv_out)
{
    __shared__ float sf[256];
    int g = blockIdx.x, t = threadIdx.x;
    sf[t]       = fused[(size_t)g * 256 + t];
    sf[t + 128] = fused[(size_t)g * 256 + 128 + t];
    __syncthreads();
    if (t < 112) {
        bool is_mu = (t < 56);
        int j = is_mu ? t : t - 56;
        const float* Wp = is_mu ? mu_w : lv_w;
        float acc = is_mu ? mu_b[j] : lv_b[j];
#pragma unroll 8
        for (int k = 0; k < 256; k++) acc += sf[k] * Wp[k * ZD + j];
        if (is_mu) mu_out[(size_t)g * ZD + j] = acc;
        else       lv_out[(size_t)g * ZD + j] = acc;
    }
}

// ---------------------------------------------------------------------------
struct Scratch {
    float *A, *B, *aggr, *sums, *cnt, *wt;
    int *rowptr, *cursor, *csrsrc, *bsums;
};

static void encode(cudaStream_t st, const Scratch& S,
                   const float* x, int n, int din, const int* ei, int E,
                   const int* batch, const float* pw, const float* pb,
                   const float* mw, const float* mb,
                   const float* lw, const float* lb,
                   float* fused, int colofs)
{
    int gb  = (n + 127) / 128;
    int nb  = (n + 1023) / 1024;
    int ebk = (E + 255) / 256;
    int wbk = (int)(((long long)n * 32 + 255) / 256);

    // ---- weight pre-conversion to tf32 ----
    const int np = din * 128, nm = 3 * 256 * 128, nl = 3 * 128 * 128;
    float* wproj = S.wt;
    float* wmsg  = S.wt + np;
    float* wlin  = wmsg + nm;
    k_cvt<<<(np + 255) / 256, 256, 0, st>>>(pw, wproj, np);
    k_cvt<<<(nm + 255) / 256, 256, 0, st>>>(mw, wmsg, nm);
    k_cvt<<<(nl + 255) / 256, 256, 0, st>>>(lw, wlin, nl);

    // ---- CSR build ----
    cudaMemsetAsync(S.rowptr, 0, (size_t)(n + 1) * sizeof(int), st);
    k_count<<<ebk, 256, 0, st>>>(ei, E, S.rowptr);
    scan_block<<<nb, 1024, 0, st>>>(S.rowptr, n, S.bsums);
    scan_tops<<<1, 128, 0, st>>>(S.bsums, nb);
    scan_add<<<nb, 1024, 0, st>>>(S.rowptr, n, S.bsums, E);
    cudaMemcpyAsync(S.cursor, S.rowptr, (size_t)n * sizeof(int),
                    cudaMemcpyDeviceToDevice, st);
    k_fill<<<ebk, 256, 0, st>>>(ei, E, S.cursor, S.csrsrc);

    // ---- layer 0 (raw input, cvt in-kernel) ----
    fused_layer<<<gb, 256, 0, st>>>(x, din, n, 1, wproj, pb,
                                    wmsg, mb, wmsg + 16384, S.A, S.B);
    csr_agg<<<wbk, 256, 0, st>>>(S.rowptr, S.csrsrc, S.A, S.B, S.aggr, n);

    // ---- layers 1..2 (aggr pre-converted, pure cp.async) ----
    for (int l = 1; l < 3; l++) {
        fused_layer<<<gb, 256, 0, st>>>(S.aggr, 128, n, 0,
                                        wlin + (size_t)(l - 1) * 16384, lb + (l - 1) * 128,
                                        wmsg + (size_t)l * 32768, mb + l * 128,
                                        wmsg + (size_t)l * 32768 + 16384, S.A, S.B);
        csr_agg<<<wbk, 256, 0, st>>>(S.rowptr, S.csrsrc, S.A, S.B, S.aggr, n);
    }

    // ---- final lin + mean-pool numerator ----
    cudaMemsetAsync(S.sums, 0, (size_t)NGRAPHS * 128 * sizeof(float), st);
    gemm_pool<<<gb, 256, 0, st>>>(S.aggr, wlin + (size_t)2 * 16384, lb + 2 * 128,
                                  n, batch, S.sums);
    cudaMemsetAsync(S.cnt, 0, (size_t)NGRAPHS * sizeof(float), st);
    pool_cnt<<<(n + 255) / 256, 256, 0, st>>>(batch, n, S.cnt);
    pool_div<<<NGRAPHS, 128, 0, st>>>(S.sums, S.cnt, fused, colofs);
}

extern "C" void kernel_launch(void* const* d_in, const int* in_sizes, int n_in,
                              void* d_out, int out_size)
{
    const float* tree_x      = (const float*)d_in[0];
    const int*   tree_ei     = (const int*)  d_in[1];
    const float* graph_x     = (const float*)d_in[2];
    const int*   graph_ei    = (const int*)  d_in[3];
    const int*   batch_tree  = (const int*)  d_in[4];
    const int*   batch_graph = (const int*)  d_in[5];
    const float* t_proj_w = (const float*)d_in[6];
    const float* t_proj_b = (const float*)d_in[7];
    const float* t_msg_w  = (const float*)d_in[8];
    const float* t_msg_b  = (const float*)d_in[9];
    const float* t_lin_w  = (const float*)d_in[10];
    const float* t_lin_b  = (const float*)d_in[11];
    const float* gr_proj_w = (const float*)d_in[12];
    const float* gr_proj_b = (const float*)d_in[13];
    const float* gr_msg_w  = (const float*)d_in[14];
    const float* gr_msg_b  = (const float*)d_in[15];
    const float* gr_lin_w  = (const float*)d_in[16];
    const float* gr_lin_b  = (const float*)d_in[17];
    const float* mu_w = (const float*)d_in[18];
    const float* mu_b = (const float*)d_in[19];
    const float* lv_w = (const float*)d_in[20];
    const float* lv_b = (const float*)d_in[21];
    float* out = (float*)d_out;

    const int n_tree  = in_sizes[0] / 64;
    const int e_tree  = in_sizes[1] / 2;
    const int n_graph = in_sizes[2] / 32;
    const int e_graph = in_sizes[3] / 2;

    Scratch G, T;
    cudaGetSymbolAddress((void**)&G.A,      g_A);
    cudaGetSymbolAddress((void**)&G.B,      g_B);
    cudaGetSymbolAddress((void**)&G.aggr,   g_aggr);
    cudaGetSymbolAddress((void**)&G.sums,   g_sums);
    cudaGetSymbolAddress((void**)&G.cnt,    g_cnt);
    cudaGetSymbolAddress((void**)&G.wt,     g_wt);
    cudaGetSymbolAddress((void**)&G.rowptr, g_rowptr);
    cudaGetSymbolAddress((void**)&G.cursor, g_cursor);
    cudaGetSymbolAddress((void**)&G.csrsrc, g_csrsrc);
    cudaGetSymbolAddress((void**)&G.bsums,  g_bsums);
    cudaGetSymbolAddress((void**)&T.A,      t_A);
    cudaGetSymbolAddress((void**)&T.B,      t_B);
    cudaGetSymbolAddress((void**)&T.aggr,   t_aggr);
    cudaGetSymbolAddress((void**)&T.sums,   t_sums);
    cudaGetSymbolAddress((void**)&T.cnt,    t_cnt);
    cudaGetSymbolAddress((void**)&T.wt,     t_wt);
    cudaGetSymbolAddress((void**)&T.rowptr, t_rowptr);
    cudaGetSymbolAddress((void**)&T.cursor, t_cursor);
    cudaGetSymbolAddress((void**)&T.csrsrc, t_csrsrc);
    cudaGetSymbolAddress((void**)&T.bsums,  t_bsums);

    static cudaStream_t s_tree = nullptr;
    static cudaEvent_t ev_fork = nullptr, ev_join = nullptr;
    if (!s_tree) {
        cudaStreamCreateWithFlags(&s_tree, cudaStreamNonBlocking);
        cudaEventCreateWithFlags(&ev_fork, cudaEventDisableTiming);
        cudaEventCreateWithFlags(&ev_join, cudaEventDisableTiming);
    }

    float* fused = out + 2 * NGRAPHS * ZD;   // output layout: mu | logvar | fused

    cudaEventRecord(ev_fork, 0);
    cudaStreamWaitEvent(s_tree, ev_fork, 0);

    encode(s_tree, T, tree_x, n_tree, 64, tree_ei, e_tree, batch_tree,
           t_proj_w, t_proj_b, t_msg_w, t_msg_b, t_lin_w, t_lin_b, fused, 0);
    encode(0, G, graph_x, n_graph, 32, graph_ei, e_graph, batch_graph,
           gr_proj_w, gr_proj_b, gr_msg_w, gr_msg_b, gr_lin_w, gr_lin_b, fused, 128);

    cudaEventRecord(ev_join, s_tree);
    cudaStreamWaitEvent(0, ev_join, 0);

    head_kernel<<<NGRAPHS, 128>>>(fused, mu_w, mu_b, lv_w, lv_b,
                                  out, out + NGRAPHS * ZD);
}